// round 9
// baseline (speedup 1.0000x reference)
#include <cuda_runtime.h>
#include <math.h>

#define N_ROI 2000
#define N_CLS 21
#define N_GT  20
#define N_PIX 1900
#define OUT_DETS (20 * N_ROI * 5)   // 200000
#define PADK 1152                   // padded sorted-box capacity
#define WMASK 36                    // PADK / 32 words per mask row

// Global scratch (no allocations allowed)
__device__ float g_part[8][3][N_PIX];
__device__ int   g_Kv[20];
__device__ __align__(16) float g_soa[6][20][PADK];   // x1,y1,x2,y2,area,score

// ---------------------------------------------------------------------------
// K1: zero output + SoA + Kv, and per-pixel channel partial sums.
// grid = 64 (chan) + 196 (out zero) + 135 (soa zero) = 395 blocks, 256 thr.
// ---------------------------------------------------------------------------
__global__ void __launch_bounds__(256) fused_pre(
    float* __restrict__ out,
    const float* __restrict__ f, const float* __restrict__ fo,
    const float* __restrict__ fr)
{
    const int tid = threadIdx.x;
    const int blk = blockIdx.x;
    if (blk < 64) {
        int chunk = blk & 7, g = blk >> 3;
        int p = chunk * 256 + tid;
        if (p >= N_PIX) return;
        const float* pf = f  + (size_t)g * 64 * N_PIX + p;
        const float* po = fo + (size_t)g * 64 * N_PIX + p;
        const float* pr = fr + (size_t)g * 64 * N_PIX + p;
        float s0 = 0.f, s1 = 0.f, s2 = 0.f;
        #pragma unroll 8
        for (int c = 0; c < 64; c++) {
            s0 += pf[(size_t)c * N_PIX];
            s1 += po[(size_t)c * N_PIX];
            s2 += pr[(size_t)c * N_PIX];
        }
        g_part[g][0][p] = s0;
        g_part[g][1][p] = s1;
        g_part[g][2][p] = s2;
    } else if (blk < 64 + 196) {
        int base = (blk - 64) * 1024 + tid * 4;
        if (base + 3 < OUT_DETS + 2) {
            *(float4*)(out + base) = make_float4(0.f, 0.f, 0.f, 0.f);
        } else {
            for (int t = 0; t < 4; t++)
                if (base + t < OUT_DETS + 2) out[base + t] = 0.0f;
        }
    } else {
        int i4 = (blk - 64 - 196) * 256 + tid;
        ((float4*)g_soa)[i4] = make_float4(0.f, 0.f, 0.f, 0.f);
        if (blk == 64 + 196 && tid < 20) g_Kv[tid] = 0;
    }
}

// ---------------------------------------------------------------------------
// K2: rank (stable sort by counting over compacted keys) + decode + scatter.
// grid (8, 20). j = blockIdx.x*256+tid is the original roi index. (verified)
// ---------------------------------------------------------------------------
__global__ void __launch_bounds__(256) rank_decode(
    const float* __restrict__ cls_prob, const float* __restrict__ rois,
    const float* __restrict__ bbox_pred, const float* __restrict__ im_info)
{
    __shared__ unsigned long long keys[N_ROI];
    __shared__ __align__(16) unsigned long long ckeys[N_ROI + 2];
    __shared__ int cnt;
    const int tid = threadIdx.x;
    const int cslot = blockIdx.y;
    const int cls = cslot + 1;

    if (tid == 0) cnt = 0;
    __syncthreads();

    for (int i = tid; i < N_ROI; i += 256) {
        float s = cls_prob[i * N_CLS + cls];
        unsigned long long k = (s > 0.5f)
            ? (((unsigned long long)__float_as_uint(s) << 32) |
               (unsigned)(0xFFFF - i))
            : 0ULL;
        keys[i] = k;
        if (k) ckeys[atomicAdd(&cnt, 1)] = k;
    }
    __syncthreads();
    const int Kv = cnt;
    if (tid == 0) {
        ckeys[Kv] = 0ULL;
        if (blockIdx.x == 0) g_Kv[cslot] = (Kv < PADK) ? Kv : PADK;
    }
    __syncthreads();

    int j = blockIdx.x * 256 + tid;
    if (j >= N_ROI) return;
    const unsigned long long kj = keys[j];
    if (kj == 0ULL) return;

    int rank = 0;
    const ulonglong2* ck2 = (const ulonglong2*)ckeys;
    const int n2 = (Kv + 1) >> 1;
    #pragma unroll 4
    for (int k = 0; k < n2; k++) {
        ulonglong2 a = ck2[k];
        rank += (a.x > kj) + (a.y > kj);
    }
    if (rank >= PADK) return;

    const float Hm1 = im_info[0] - 1.0f;
    const float Wm1 = im_info[1] - 1.0f;
    float x1 = rois[j * 5 + 1], y1 = rois[j * 5 + 2];
    float x2 = rois[j * 5 + 3], y2 = rois[j * 5 + 4];
    float w = x2 - x1 + 1.0f, h = y2 - y1 + 1.0f;
    float cx = x1 + 0.5f * w, cy = y1 + 0.5f * h;
    const float* d = bbox_pred + ((size_t)j * N_CLS + (size_t)cls) * 4;
    float dx = d[0] * 0.1f, dy = d[1] * 0.1f;
    float dw = d[2] * 0.2f, dh = d[3] * 0.2f;
    float pcx = dx * w + cx, pcy = dy * h + cy;
    float pw = expf(dw) * w, ph = expf(dh) * h;
    float px1 = fminf(fmaxf(pcx - 0.5f * pw, 0.0f), Wm1);
    float py1 = fminf(fmaxf(pcy - 0.5f * ph, 0.0f), Hm1);
    float px2 = fminf(fmaxf(pcx + 0.5f * pw, 0.0f), Wm1);
    float py2 = fminf(fmaxf(pcy + 0.5f * ph, 0.0f), Hm1);

    g_soa[0][cslot][rank] = px1;
    g_soa[1][cslot][rank] = py1;
    g_soa[2][cslot][rank] = px2;
    g_soa[3][cslot][rank] = py2;
    g_soa[4][cslot][rank] = (px2 - px1) * (py2 - py1);
    g_soa[5][cslot][rank] = __uint_as_float((unsigned)(kj >> 32));
}

// ---------------------------------------------------------------------------
// K3: per-class mask build (in shared) + two-level greedy resolve + GT dedup
// + output. Block 20 does the loss finalize. grid 21, 1024 threads.
// ---------------------------------------------------------------------------
__global__ void __launch_bounds__(1024) nms_class(
    const float* __restrict__ gt_boxes, const int* __restrict__ num_boxes,
    float* __restrict__ out)
{
    const int tid  = threadIdx.x;

    // ---- block 20: loss finalize (verified arithmetic) ----
    if (blockIdx.x == 20) {
        __shared__ float red[256];
        if (tid >= 256) return;
        float a0 = 0.f, a1 = 0.f, a2 = 0.f, a3 = 0.f, a4 = 0.f;
        for (int p = tid; p < N_PIX; p += 256) {
            float mf = 0.f, mo = 0.f, mr = 0.f;
            #pragma unroll
            for (int g = 0; g < 8; g++) {
                mf += g_part[g][0][p];
                mo += g_part[g][1][p];
                mr += g_part[g][2][p];
            }
            mf *= (1.0f / 512.0f); mo *= (1.0f / 512.0f); mr *= (1.0f / 512.0f);
            a0 += mf * mf;
            a1 += mo * mo;
            float d = mf - mo; a2 += d * d;
            a3 += mr * mr;
            float s = mo + mr; a4 += s * s;
        }
        float acc[5] = {a0, a1, a2, a3, a4};
        float tot[5];
        for (int t = 0; t < 5; t++) {
            red[tid] = acc[t];
            __syncthreads();
            for (int off = 128; off > 0; off >>= 1) {
                if (tid < off) red[tid] += red[tid + off];
                __syncthreads();
            }
            tot[t] = red[0];
            __syncthreads();
        }
        if (tid == 0) {
            float n_f  = sqrtf(tot[0]);
            float n_fo = sqrtf(tot[1]);
            float distil   = fabsf(n_f - n_fo);
            float res_loss = fabsf(sqrtf(tot[2]) - sqrtf(tot[3]));
            float res_inc  = fabsf(sqrtf(tot[4]) - n_f);
            out[OUT_DETS + 0] = distil;
            out[OUT_DETS + 1] = res_inc + res_loss;
        }
        return;
    }

    extern __shared__ unsigned char smraw[];
    unsigned* smask = (unsigned*)smraw;                 // [PADK*WMASK]
    float*    sx1   = (float*)(smask + PADK * WMASK);   // [PADK] x6
    float*    sy1   = sx1 + PADK;
    float*    sx2   = sy1 + PADK;
    float*    sy2   = sx2 + PADK;
    float*    sar   = sy2 + PADK;
    float*    ssc   = sar + PADK;
    float4*   sgt   = (float4*)(ssc + PADK);            // [N_GT]
    unsigned* sup   = (unsigned*)(sgt + N_GT);          // [64]
    __shared__ int sNum;

    const int lane = tid & 31;
    const int wid  = tid >> 5;
    const int cslot = blockIdx.x;
    const int Kv = g_Kv[cslot];
    const int W = (Kv + 31) >> 5;

    // SoA load (vectorized)
    for (int a = 0; a < 6; a++) {
        const float4* s4 = (const float4*)&g_soa[a][cslot][0];
        float4* d4 = (float4*)(sx1 + (size_t)a * PADK);
        for (int i = tid; i < PADK / 4; i += 1024) d4[i] = s4[i];
    }
    if (tid < N_GT * 4)
        ((float*)sgt)[tid] = gt_boxes[(tid >> 2) * 5 + (tid & 3)];
    if (tid >= 128 && tid < 192) sup[tid - 128] = 0u;
    if (tid == 0) {
        int nb = num_boxes[0];
        sNum = nb < 0 ? 0 : (nb > N_GT ? N_GT : nb);
    }
    __syncthreads();

    if (Kv > 0) {
        // ---- mask build straight into shared (warp-per-row) ----
        for (int row = wid; row < Kv; row += 32) {
            const int dw = row >> 5;
            const float bx1 = sx1[row], by1 = sy1[row];
            const float bx2 = sx2[row], by2 = sy2[row], ba = sar[row];
            for (int word = dw; word < W; word++) {
                int k = (word << 5) + lane;
                float lx = fmaxf(bx1, sx1[k]), ly = fmaxf(by1, sy1[k]);
                float rx = fminf(bx2, sx2[k]), ry = fminf(by2, sy2[k]);
                float ww = fmaxf(rx - lx, 0.0f), hh = fmaxf(ry - ly, 0.0f);
                float inter = ww * hh;
                float iou = inter / (ba + sar[k] - inter + 1e-6f);
                bool p = iou > 0.3f;
                if (word == dw) p = p && (k > row);
                unsigned wbits = __ballot_sync(0xffffffffu, p);
                if (lane == 0) smask[row * WMASK + word] = wbits;
            }
        }
        __syncthreads();

        // ---- two-level greedy resolve (warp 0) ----
        // Register state: lane l owns suppression words l (s_lo) and l+32 (s_hi).
        if (wid == 0) {
            unsigned s_lo = 0u, s_hi = 0u;
            const int lastj = (Kv - 1) >> 5;
            const unsigned tailm = (Kv & 31) ? (~0u << (Kv & 31)) : 0u;
            for (int j = 0; j <= lastj; j++) {
                unsigned wj = (j < 32) ? __shfl_sync(0xffffffffu, s_lo, j)
                                       : __shfl_sync(0xffffffffu, s_hi, j - 32);
                // preload diagonal words: lane b holds row (j*32+b)'s word j
                int rowb = (j << 5) + lane;
                unsigned dj = (rowb < Kv) ? smask[rowb * WMASK + j] : 0u;
                unsigned proc = (j == lastj) ? tailm : 0u;
                unsigned km = 0u;
                unsigned cand = ~(wj | proc);
                // shfl-only serial chain (~32cyc per kept bit)
                while (cand) {
                    int b = __ffs(cand) - 1;
                    km  |= (1u << b);
                    proc |= (1u << b);
                    unsigned rd = __shfl_sync(0xffffffffu, dj, b);
                    wj |= rd;
                    cand = ~(wj | proc);
                }
                // deferred parallel OR of kept rows (independent LDS, off-chain)
                unsigned t = km;
                while (t) {
                    int b = __ffs(t) - 1; t &= t - 1;
                    const unsigned* row = smask + ((j << 5) + b) * WMASK;
                    if (lane >= j && lane < W) s_lo |= row[lane];
                    int l2 = lane + 32;
                    if (l2 >= j && l2 < W) s_hi |= row[l2];
                }
                // commit word j's final value (includes in-word suppression)
                if (j < 32) { if (lane == j) s_lo = wj; }
                else        { if (lane == j - 32) s_hi = wj; }
            }
            sup[lane] = s_lo;
            if (lane < 32) sup[32 + lane] = s_hi;
        }
        __syncthreads();

        // ---- GT dedup + output ----
        float* outc = out + (size_t)cslot * N_ROI * 5;
        const int numgt = sNum;
        for (int i = tid; i < Kv; i += 1024) {
            if (!((sup[i >> 5] >> (i & 31)) & 1u)) {
                float bx1 = sx1[i], by1 = sy1[i], bx2 = sx2[i], by2 = sy2[i];
                float ba = sar[i];
                bool hit = false;
                for (int g = 0; g < numgt; g++) {
                    float4 c = sgt[g];
                    float areaB = (c.z - c.x) * (c.w - c.y);
                    float lx = fmaxf(bx1, c.x), ly = fmaxf(by1, c.y);
                    float rx = fminf(bx2, c.z), ry = fminf(by2, c.w);
                    float ww = fmaxf(rx - lx, 0.0f), hh = fmaxf(ry - ly, 0.0f);
                    float inter = ww * hh;
                    float iou = inter / (ba + areaB - inter + 1e-6f);
                    hit = hit || (iou > 0.3f);
                }
                if (!hit) {
                    outc[(size_t)i * 5 + 0] = bx1;
                    outc[(size_t)i * 5 + 1] = by1;
                    outc[(size_t)i * 5 + 2] = bx2;
                    outc[(size_t)i * 5 + 3] = by2;
                    outc[(size_t)i * 5 + 4] = ssc[i];
                }
            }
        }
    }
}

extern "C" void kernel_launch(void* const* d_in, const int* in_sizes, int n_in,
                              void* d_out, int out_size) {
    const float* rois      = (const float*)d_in[0];
    const float* cls_prob  = (const float*)d_in[1];
    const float* bbox_pred = (const float*)d_in[2];
    const float* im_info   = (const float*)d_in[3];
    const float* gt_boxes  = (const float*)d_in[4];
    const int*   num_boxes = (const int*)d_in[5];
    const float* feat      = (const float*)d_in[6];
    const float* feat_org  = (const float*)d_in[7];
    const float* feat_res  = (const float*)d_in[8];
    float* out = (float*)d_out;

    const int smem = (int)(PADK * WMASK * sizeof(unsigned)   // 165888
                         + 6 * PADK * sizeof(float)          //  27648
                         + N_GT * sizeof(float4)             //    320
                         + 64 * sizeof(unsigned));           //    256
    static int configured = 0;
    if (!configured) {
        cudaFuncSetAttribute(nms_class,
                             cudaFuncAttributeMaxDynamicSharedMemorySize, smem);
        configured = 1;
    }

    fused_pre<<<395, 256>>>(out, feat, feat_org, feat_res);
    rank_decode<<<dim3(8, 20), 256>>>(cls_prob, rois, bbox_pred, im_info);
    nms_class<<<21, 1024, smem>>>(gt_boxes, num_boxes, out);
}

// round 11
// speedup vs baseline: 2.0077x; 2.0077x over previous
#include <cuda_runtime.h>
#include <math.h>

#define N_ROI 2000
#define N_CLS 21
#define N_GT  20
#define N_PIX 1900
#define OUT_DETS (20 * N_ROI * 5)   // 200000
#define PADK 1152                   // padded sorted-box capacity
#define WMASK 36                    // PADK / 32 words per mask row
#define ROWS_PER_BLK 72             // PADK / 16 row tiles for mask_build
#define NGRP 32                     // channel groups (16 channels each)

// Global scratch (no allocations allowed)
__device__ float g_part[NGRP][3][N_PIX];
__device__ int   g_Kv[20];
__device__ __align__(16) float    g_soa[6][20][PADK];   // x1,y1,x2,y2,area,score
__device__ __align__(16) unsigned g_mk[20][PADK][WMASK];

// ---------------------------------------------------------------------------
// K1: channel partial sums (256 blocks) + zero output (196) + zero SoA (135).
// grid = 587 blocks, 256 threads.
// ---------------------------------------------------------------------------
__global__ void __launch_bounds__(256) fused_pre(
    float* __restrict__ out,
    const float* __restrict__ f, const float* __restrict__ fo,
    const float* __restrict__ fr)
{
    const int tid = threadIdx.x;
    const int blk = blockIdx.x;
    if (blk < 256) {
        int chunk = blk & 7, g = blk >> 3;       // g in [0,32)
        int p = chunk * 256 + tid;
        if (p >= N_PIX) return;
        const float* pf = f  + (size_t)g * 16 * N_PIX + p;
        const float* po = fo + (size_t)g * 16 * N_PIX + p;
        const float* pr = fr + (size_t)g * 16 * N_PIX + p;
        float s0 = 0.f, s1 = 0.f, s2 = 0.f;
        #pragma unroll 16
        for (int c = 0; c < 16; c++) {
            s0 += pf[(size_t)c * N_PIX];
            s1 += po[(size_t)c * N_PIX];
            s2 += pr[(size_t)c * N_PIX];
        }
        g_part[g][0][p] = s0;
        g_part[g][1][p] = s1;
        g_part[g][2][p] = s2;
    } else if (blk < 256 + 196) {
        int base = (blk - 256) * 1024 + tid * 4;
        if (base + 3 < OUT_DETS + 2) {
            *(float4*)(out + base) = make_float4(0.f, 0.f, 0.f, 0.f);
        } else {
            for (int t = 0; t < 4; t++)
                if (base + t < OUT_DETS + 2) out[base + t] = 0.0f;
        }
    } else {
        int i4 = (blk - 256 - 196) * 256 + tid;
        ((float4*)g_soa)[i4] = make_float4(0.f, 0.f, 0.f, 0.f);
        if (blk == 256 + 196 && tid < 20) g_Kv[tid] = 0;
    }
}

// ---------------------------------------------------------------------------
// K2: rank (stable sort by counting over compacted keys) + decode + scatter.
// grid (8, 20). j = blockIdx.x*256+tid is the original roi index. (verified)
// ---------------------------------------------------------------------------
__global__ void __launch_bounds__(256) rank_decode(
    const float* __restrict__ cls_prob, const float* __restrict__ rois,
    const float* __restrict__ bbox_pred, const float* __restrict__ im_info)
{
    __shared__ unsigned long long keys[N_ROI];
    __shared__ __align__(16) unsigned long long ckeys[N_ROI + 2];
    __shared__ int cnt;
    const int tid = threadIdx.x;
    const int cslot = blockIdx.y;
    const int cls = cslot + 1;

    if (tid == 0) cnt = 0;
    __syncthreads();

    for (int i = tid; i < N_ROI; i += 256) {
        float s = cls_prob[i * N_CLS + cls];
        unsigned long long k = (s > 0.5f)
            ? (((unsigned long long)__float_as_uint(s) << 32) |
               (unsigned)(0xFFFF - i))
            : 0ULL;
        keys[i] = k;
        if (k) ckeys[atomicAdd(&cnt, 1)] = k;
    }
    __syncthreads();
    const int Kv = cnt;
    if (tid == 0) {
        ckeys[Kv] = 0ULL;
        if (blockIdx.x == 0) g_Kv[cslot] = (Kv < PADK) ? Kv : PADK;
    }
    __syncthreads();

    int j = blockIdx.x * 256 + tid;
    if (j >= N_ROI) return;
    const unsigned long long kj = keys[j];
    if (kj == 0ULL) return;

    int rank = 0;
    const ulonglong2* ck2 = (const ulonglong2*)ckeys;
    const int n2 = (Kv + 1) >> 1;
    #pragma unroll 4
    for (int k = 0; k < n2; k++) {
        ulonglong2 a = ck2[k];
        rank += (a.x > kj) + (a.y > kj);
    }
    if (rank >= PADK) return;

    const float Hm1 = im_info[0] - 1.0f;
    const float Wm1 = im_info[1] - 1.0f;
    float x1 = rois[j * 5 + 1], y1 = rois[j * 5 + 2];
    float x2 = rois[j * 5 + 3], y2 = rois[j * 5 + 4];
    float w = x2 - x1 + 1.0f, h = y2 - y1 + 1.0f;
    float cx = x1 + 0.5f * w, cy = y1 + 0.5f * h;
    const float* d = bbox_pred + ((size_t)j * N_CLS + (size_t)cls) * 4;
    float dx = d[0] * 0.1f, dy = d[1] * 0.1f;
    float dw = d[2] * 0.2f, dh = d[3] * 0.2f;
    float pcx = dx * w + cx, pcy = dy * h + cy;
    float pw = expf(dw) * w, ph = expf(dh) * h;
    float px1 = fminf(fmaxf(pcx - 0.5f * pw, 0.0f), Wm1);
    float py1 = fminf(fmaxf(pcy - 0.5f * ph, 0.0f), Hm1);
    float px2 = fminf(fmaxf(pcx + 0.5f * pw, 0.0f), Wm1);
    float py2 = fminf(fmaxf(pcy + 0.5f * ph, 0.0f), Hm1);

    g_soa[0][cslot][rank] = px1;
    g_soa[1][cslot][rank] = py1;
    g_soa[2][cslot][rank] = px2;
    g_soa[3][cslot][rank] = py2;
    g_soa[4][cslot][rank] = (px2 - px1) * (py2 - py1);
    g_soa[5][cslot][rank] = __uint_as_float((unsigned)(kj >> 32));
}

// ---------------------------------------------------------------------------
// K3: pairwise suppression mask, full-chip. grid (16, 20), 256 threads.
// Warp-per-row, diagonal-onward words; one IoU per lane, ballot-packed.
// Words < diagonal are NOT written (resolve guards its reads). (verified)
// ---------------------------------------------------------------------------
__global__ void __launch_bounds__(256) mask_build()
{
    __shared__ float sx1[PADK], sy1[PADK], sx2[PADK], sy2[PADK], sar[PADK];
    const int tid  = threadIdx.x;
    const int lane = tid & 31;
    const int wid  = tid >> 5;
    const int cslot = blockIdx.y;
    const int Kv = g_Kv[cslot];
    const int row0 = blockIdx.x * ROWS_PER_BLK;
    if (row0 >= Kv) return;
    const int rowend = (row0 + ROWS_PER_BLK < Kv) ? row0 + ROWS_PER_BLK : Kv;
    const int W = (Kv + 31) >> 5;

    for (int i = tid; i < PADK; i += 256) {
        sx1[i] = g_soa[0][cslot][i];
        sy1[i] = g_soa[1][cslot][i];
        sx2[i] = g_soa[2][cslot][i];
        sy2[i] = g_soa[3][cslot][i];
        sar[i] = g_soa[4][cslot][i];
    }
    __syncthreads();

    for (int row = row0 + wid; row < rowend; row += 8) {
        const int dw = row >> 5;
        const float bx1 = sx1[row], by1 = sy1[row];
        const float bx2 = sx2[row], by2 = sy2[row], ba = sar[row];
        for (int word = dw; word < W; word++) {
            int k = (word << 5) + lane;
            float lx = fmaxf(bx1, sx1[k]), ly = fmaxf(by1, sy1[k]);
            float rx = fminf(bx2, sx2[k]), ry = fminf(by2, sy2[k]);
            float ww = fmaxf(rx - lx, 0.0f), hh = fmaxf(ry - ly, 0.0f);
            float inter = ww * hh;
            float iou = inter / (ba + sar[k] - inter + 1e-6f);
            bool p = iou > 0.3f;
            if (word == dw) p = p && (k > row);
            unsigned wbits = __ballot_sync(0xffffffffu, p);
            if (lane == 0) g_mk[cslot][row][word] = wbits;
        }
    }
}

// ---------------------------------------------------------------------------
// K4: per-class two-level greedy resolve + GT dedup + output (blocks 0-19);
// block 20 does the loss finalize. grid 21, 1024 threads.
// ---------------------------------------------------------------------------
__global__ void __launch_bounds__(1024) resolve_out(
    const float* __restrict__ gt_boxes, const int* __restrict__ num_boxes,
    float* __restrict__ out)
{
    const int tid = threadIdx.x;

    // ---- block 20: loss finalize ----
    if (blockIdx.x == 20) {
        __shared__ float red[256];
        if (tid >= 256) return;
        float a0 = 0.f, a1 = 0.f, a2 = 0.f, a3 = 0.f, a4 = 0.f;
        for (int p = tid; p < N_PIX; p += 256) {
            float mf = 0.f, mo = 0.f, mr = 0.f;
            #pragma unroll
            for (int g = 0; g < NGRP; g++) {
                mf += g_part[g][0][p];
                mo += g_part[g][1][p];
                mr += g_part[g][2][p];
            }
            mf *= (1.0f / 512.0f); mo *= (1.0f / 512.0f); mr *= (1.0f / 512.0f);
            a0 += mf * mf;
            a1 += mo * mo;
            float d = mf - mo; a2 += d * d;
            a3 += mr * mr;
            float s = mo + mr; a4 += s * s;
        }
        float acc[5] = {a0, a1, a2, a3, a4};
        float tot[5];
        for (int t = 0; t < 5; t++) {
            red[tid] = acc[t];
            __syncthreads();
            for (int off = 128; off > 0; off >>= 1) {
                if (tid < off) red[tid] += red[tid + off];
                __syncthreads();
            }
            tot[t] = red[0];
            __syncthreads();
        }
        if (tid == 0) {
            float n_f  = sqrtf(tot[0]);
            float n_fo = sqrtf(tot[1]);
            float distil   = fabsf(n_f - n_fo);
            float res_loss = fabsf(sqrtf(tot[2]) - sqrtf(tot[3]));
            float res_inc  = fabsf(sqrtf(tot[4]) - n_f);
            out[OUT_DETS + 0] = distil;
            out[OUT_DETS + 1] = res_inc + res_loss;
        }
        return;
    }

    extern __shared__ unsigned char smraw[];
    unsigned* smask = (unsigned*)smraw;                 // [PADK*WMASK]
    float*    sx1   = (float*)(smask + PADK * WMASK);   // [PADK] x6
    float*    sy1   = sx1 + PADK;
    float*    sx2   = sy1 + PADK;
    float*    sy2   = sx2 + PADK;
    float*    sar   = sy2 + PADK;
    float*    ssc   = sar + PADK;
    float4*   sgt   = (float4*)(ssc + PADK);            // [N_GT]
    unsigned* sup   = (unsigned*)(sgt + N_GT);          // [64]
    __shared__ int sNum;

    const int lane = tid & 31;
    const int wid  = tid >> 5;
    const int cslot = blockIdx.x;
    const int Kv = g_Kv[cslot];
    const int W = (Kv + 31) >> 5;

    for (int a = 0; a < 6; a++) {
        const float4* s4 = (const float4*)&g_soa[a][cslot][0];
        float4* d4 = (float4*)(sx1 + (size_t)a * PADK);
        for (int i = tid; i < PADK / 4; i += 1024) d4[i] = s4[i];
    }
    {   // mask copy (uint4 bulk, parallel)
        const uint4* s4 = (const uint4*)&g_mk[cslot][0][0];
        uint4* d4 = (uint4*)smask;
        const int n4 = (Kv * WMASK + 3) >> 2;
        for (int i = tid; i < n4; i += 1024) d4[i] = s4[i];
    }
    if (tid < N_GT * 4)
        ((float*)sgt)[tid] = gt_boxes[(tid >> 2) * 5 + (tid & 3)];
    if (tid >= 128 && tid < 192) sup[tid - 128] = 0u;
    if (tid == 0) {
        int nb = num_boxes[0];
        sNum = nb < 0 ? 0 : (nb > N_GT ? N_GT : nb);
    }
    __syncthreads();

    if (Kv > 0) {
        // ---- two-level greedy resolve (warp 0), verified in R8 ----
        if (wid == 0) {
            unsigned s_lo = 0u, s_hi = 0u;   // lane owns words lane, lane+32
            const int lastj = (Kv - 1) >> 5;
            const unsigned tailm = (Kv & 31) ? (~0u << (Kv & 31)) : 0u;
            for (int j = 0; j <= lastj; j++) {
                unsigned wj = (j < 32) ? __shfl_sync(0xffffffffu, s_lo, j)
                                       : __shfl_sync(0xffffffffu, s_hi, j - 32);
                int rowb = (j << 5) + lane;   // preload diagonal words
                unsigned dj = (rowb < Kv) ? smask[rowb * WMASK + j] : 0u;
                unsigned proc = (j == lastj) ? tailm : 0u;
                unsigned km = 0u;
                unsigned cand = ~(wj | proc);
                while (cand) {                // shfl-only serial chain
                    int b = __ffs(cand) - 1;
                    km  |= (1u << b);
                    proc |= (1u << b);
                    unsigned rd = __shfl_sync(0xffffffffu, dj, b);
                    wj |= rd;
                    cand = ~(wj | proc);
                }
                unsigned t = km;              // deferred pipelined row ORs
                while (t) {
                    int b = __ffs(t) - 1; t &= t - 1;
                    const unsigned* row = smask + ((j << 5) + b) * WMASK;
                    if (lane >= j && lane < W) s_lo |= row[lane];
                    int l2 = lane + 32;
                    if (l2 >= j && l2 < W) s_hi |= row[l2];
                }
                if (j < 32) { if (lane == j) s_lo = wj; }
                else        { if (lane == j - 32) s_hi = wj; }
            }
            sup[lane] = s_lo;
            sup[32 + lane] = s_hi;
        }
        __syncthreads();

        // ---- GT dedup + output ----
        float* outc = out + (size_t)cslot * N_ROI * 5;
        const int numgt = sNum;
        for (int i = tid; i < Kv; i += 1024) {
            if (!((sup[i >> 5] >> (i & 31)) & 1u)) {
                float bx1 = sx1[i], by1 = sy1[i], bx2 = sx2[i], by2 = sy2[i];
                float ba = sar[i];
                bool hit = false;
                for (int g = 0; g < numgt; g++) {
                    float4 c = sgt[g];
                    float areaB = (c.z - c.x) * (c.w - c.y);
                    float lx = fmaxf(bx1, c.x), ly = fmaxf(by1, c.y);
                    float rx = fminf(bx2, c.z), ry = fminf(by2, c.w);
                    float ww = fmaxf(rx - lx, 0.0f), hh = fmaxf(ry - ly, 0.0f);
                    float inter = ww * hh;
                    float iou = inter / (ba + areaB - inter + 1e-6f);
                    hit = hit || (iou > 0.3f);
                }
                if (!hit) {
                    outc[(size_t)i * 5 + 0] = bx1;
                    outc[(size_t)i * 5 + 1] = by1;
                    outc[(size_t)i * 5 + 2] = bx2;
                    outc[(size_t)i * 5 + 3] = by2;
                    outc[(size_t)i * 5 + 4] = ssc[i];
                }
            }
        }
    }
}

extern "C" void kernel_launch(void* const* d_in, const int* in_sizes, int n_in,
                              void* d_out, int out_size) {
    const float* rois      = (const float*)d_in[0];
    const float* cls_prob  = (const float*)d_in[1];
    const float* bbox_pred = (const float*)d_in[2];
    const float* im_info   = (const float*)d_in[3];
    const float* gt_boxes  = (const float*)d_in[4];
    const int*   num_boxes = (const int*)d_in[5];
    const float* feat      = (const float*)d_in[6];
    const float* feat_org  = (const float*)d_in[7];
    const float* feat_res  = (const float*)d_in[8];
    float* out = (float*)d_out;

    const int smem_res = (int)(PADK * WMASK * sizeof(unsigned)   // 165888
                             + 6 * PADK * sizeof(float)          //  27648
                             + N_GT * sizeof(float4)             //    320
                             + 64 * sizeof(unsigned));           //    256
    static int configured = 0;
    if (!configured) {
        cudaFuncSetAttribute(resolve_out,
                             cudaFuncAttributeMaxDynamicSharedMemorySize,
                             smem_res);
        configured = 1;
    }

    fused_pre<<<587, 256>>>(out, feat, feat_org, feat_res);
    rank_decode<<<dim3(8, 20), 256>>>(cls_prob, rois, bbox_pred, im_info);
    mask_build<<<dim3(16, 20), 256>>>();
    resolve_out<<<21, 1024, smem_res>>>(gt_boxes, num_boxes, out);
}

// round 12
// speedup vs baseline: 2.0746x; 1.0333x over previous
#include <cuda_runtime.h>
#include <math.h>

#define N_ROI 2000
#define N_CLS 21
#define N_GT  20
#define N_PIX 1900
#define OUT_DETS (20 * N_ROI * 5)   // 200000
#define PADK 1152                   // padded sorted-box capacity
#define WMASK 36                    // PADK / 32 words per mask row
#define ROWS_PER_BLK 72             // PADK / 16 row tiles for mask_build
#define NGRP 32                     // channel groups (16 channels each)

// Global scratch (no allocations allowed)
__device__ float g_part[NGRP][3][N_PIX];
__device__ int   g_Kv[20];
__device__ __align__(16) float    g_soa[6][20][PADK];   // x1,y1,x2,y2,area,score
__device__ __align__(16) unsigned g_mk[20][PADK][WMASK];

// ---------------------------------------------------------------------------
// K1: channel partial sums (256 blocks) + zero output (196 blocks).
// SoA / Kv zeroing dropped: garbage padding only produces mask bits >= Kv,
// which the resolve tail-mask suppresses; g_Kv is written unconditionally.
// ---------------------------------------------------------------------------
__global__ void __launch_bounds__(256) fused_pre(
    float* __restrict__ out,
    const float* __restrict__ f, const float* __restrict__ fo,
    const float* __restrict__ fr)
{
    const int tid = threadIdx.x;
    const int blk = blockIdx.x;
    if (blk < 256) {
        int chunk = blk & 7, g = blk >> 3;       // g in [0,32)
        int p = chunk * 256 + tid;
        if (p >= N_PIX) return;
        const float* pf = f  + (size_t)g * 16 * N_PIX + p;
        const float* po = fo + (size_t)g * 16 * N_PIX + p;
        const float* pr = fr + (size_t)g * 16 * N_PIX + p;
        float s0 = 0.f, s1 = 0.f, s2 = 0.f;
        #pragma unroll 16
        for (int c = 0; c < 16; c++) {
            s0 += pf[(size_t)c * N_PIX];
            s1 += po[(size_t)c * N_PIX];
            s2 += pr[(size_t)c * N_PIX];
        }
        g_part[g][0][p] = s0;
        g_part[g][1][p] = s1;
        g_part[g][2][p] = s2;
    } else {
        int base = (blk - 256) * 1024 + tid * 4;
        if (base + 3 < OUT_DETS + 2) {
            *(float4*)(out + base) = make_float4(0.f, 0.f, 0.f, 0.f);
        } else {
            for (int t = 0; t < 4; t++)
                if (base + t < OUT_DETS + 2) out[base + t] = 0.0f;
        }
    }
}

// ---------------------------------------------------------------------------
// K2: rank (stable sort by counting over compacted keys) + decode + scatter.
// grid (8, 20). j = blockIdx.x*256+tid is the original roi index. (verified)
// ---------------------------------------------------------------------------
__global__ void __launch_bounds__(256) rank_decode(
    const float* __restrict__ cls_prob, const float* __restrict__ rois,
    const float* __restrict__ bbox_pred, const float* __restrict__ im_info)
{
    __shared__ unsigned long long keys[N_ROI];
    __shared__ __align__(16) unsigned long long ckeys[N_ROI + 2];
    __shared__ int cnt;
    const int tid = threadIdx.x;
    const int cslot = blockIdx.y;
    const int cls = cslot + 1;

    if (tid == 0) cnt = 0;
    __syncthreads();

    for (int i = tid; i < N_ROI; i += 256) {
        float s = cls_prob[i * N_CLS + cls];
        unsigned long long k = (s > 0.5f)
            ? (((unsigned long long)__float_as_uint(s) << 32) |
               (unsigned)(0xFFFF - i))
            : 0ULL;
        keys[i] = k;
        if (k) ckeys[atomicAdd(&cnt, 1)] = k;
    }
    __syncthreads();
    const int Kv = cnt;
    if (tid == 0) {
        ckeys[Kv] = 0ULL;
        if (blockIdx.x == 0) g_Kv[cslot] = (Kv < PADK) ? Kv : PADK;
    }
    __syncthreads();

    int j = blockIdx.x * 256 + tid;
    if (j >= N_ROI) return;
    const unsigned long long kj = keys[j];
    if (kj == 0ULL) return;

    int rank = 0;
    const ulonglong2* ck2 = (const ulonglong2*)ckeys;
    const int n2 = (Kv + 1) >> 1;
    #pragma unroll 4
    for (int k = 0; k < n2; k++) {
        ulonglong2 a = ck2[k];
        rank += (a.x > kj) + (a.y > kj);
    }
    if (rank >= PADK) return;

    const float Hm1 = im_info[0] - 1.0f;
    const float Wm1 = im_info[1] - 1.0f;
    float x1 = rois[j * 5 + 1], y1 = rois[j * 5 + 2];
    float x2 = rois[j * 5 + 3], y2 = rois[j * 5 + 4];
    float w = x2 - x1 + 1.0f, h = y2 - y1 + 1.0f;
    float cx = x1 + 0.5f * w, cy = y1 + 0.5f * h;
    const float* d = bbox_pred + ((size_t)j * N_CLS + (size_t)cls) * 4;
    float dx = d[0] * 0.1f, dy = d[1] * 0.1f;
    float dw = d[2] * 0.2f, dh = d[3] * 0.2f;
    float pcx = dx * w + cx, pcy = dy * h + cy;
    float pw = expf(dw) * w, ph = expf(dh) * h;
    float px1 = fminf(fmaxf(pcx - 0.5f * pw, 0.0f), Wm1);
    float py1 = fminf(fmaxf(pcy - 0.5f * ph, 0.0f), Hm1);
    float px2 = fminf(fmaxf(pcx + 0.5f * pw, 0.0f), Wm1);
    float py2 = fminf(fmaxf(pcy + 0.5f * ph, 0.0f), Hm1);

    g_soa[0][cslot][rank] = px1;
    g_soa[1][cslot][rank] = py1;
    g_soa[2][cslot][rank] = px2;
    g_soa[3][cslot][rank] = py2;
    g_soa[4][cslot][rank] = (px2 - px1) * (py2 - py1);
    g_soa[5][cslot][rank] = __uint_as_float((unsigned)(kj >> 32));
}

// ---------------------------------------------------------------------------
// K3: pairwise suppression mask, full-chip. grid (16, 20), 256 threads.
// (verified) Diagonal word excludes self/lower bits via k > row.
// ---------------------------------------------------------------------------
__global__ void __launch_bounds__(256) mask_build()
{
    __shared__ float sx1[PADK], sy1[PADK], sx2[PADK], sy2[PADK], sar[PADK];
    const int tid  = threadIdx.x;
    const int lane = tid & 31;
    const int wid  = tid >> 5;
    const int cslot = blockIdx.y;
    const int Kv = g_Kv[cslot];
    const int row0 = blockIdx.x * ROWS_PER_BLK;
    if (row0 >= Kv) return;
    const int rowend = (row0 + ROWS_PER_BLK < Kv) ? row0 + ROWS_PER_BLK : Kv;
    const int W = (Kv + 31) >> 5;

    for (int i = tid; i < PADK; i += 256) {
        sx1[i] = g_soa[0][cslot][i];
        sy1[i] = g_soa[1][cslot][i];
        sx2[i] = g_soa[2][cslot][i];
        sy2[i] = g_soa[3][cslot][i];
        sar[i] = g_soa[4][cslot][i];
    }
    __syncthreads();

    for (int row = row0 + wid; row < rowend; row += 8) {
        const int dw = row >> 5;
        const float bx1 = sx1[row], by1 = sy1[row];
        const float bx2 = sx2[row], by2 = sy2[row], ba = sar[row];
        for (int word = dw; word < W; word++) {
            int k = (word << 5) + lane;
            float lx = fmaxf(bx1, sx1[k]), ly = fmaxf(by1, sy1[k]);
            float rx = fminf(bx2, sx2[k]), ry = fminf(by2, sy2[k]);
            float ww = fmaxf(rx - lx, 0.0f), hh = fmaxf(ry - ly, 0.0f);
            float inter = ww * hh;
            float iou = inter / (ba + sar[k] - inter + 1e-6f);
            bool p = iou > 0.3f;
            if (word == dw) p = p && (k > row);
            unsigned wbits = __ballot_sync(0xffffffffu, p);
            if (lane == 0) g_mk[cslot][row][word] = wbits;
        }
    }
}

// ---------------------------------------------------------------------------
// K4: per-class greedy resolve (branchless bit-serial chain) + GT dedup +
// output (blocks 0-19); block 20 does the loss finalize. grid 21, 512 thr.
// ---------------------------------------------------------------------------
__global__ void __launch_bounds__(512) resolve_out(
    const float* __restrict__ gt_boxes, const int* __restrict__ num_boxes,
    float* __restrict__ out)
{
    const int tid = threadIdx.x;

    // ---- block 20: loss finalize ----
    if (blockIdx.x == 20) {
        __shared__ float red[256];
        if (tid >= 256) return;
        float a0 = 0.f, a1 = 0.f, a2 = 0.f, a3 = 0.f, a4 = 0.f;
        for (int p = tid; p < N_PIX; p += 256) {
            float mf = 0.f, mo = 0.f, mr = 0.f;
            #pragma unroll
            for (int g = 0; g < NGRP; g++) {
                mf += g_part[g][0][p];
                mo += g_part[g][1][p];
                mr += g_part[g][2][p];
            }
            mf *= (1.0f / 512.0f); mo *= (1.0f / 512.0f); mr *= (1.0f / 512.0f);
            a0 += mf * mf;
            a1 += mo * mo;
            float d = mf - mo; a2 += d * d;
            a3 += mr * mr;
            float s = mo + mr; a4 += s * s;
        }
        float acc[5] = {a0, a1, a2, a3, a4};
        float tot[5];
        for (int t = 0; t < 5; t++) {
            red[tid] = acc[t];
            __syncthreads();
            for (int off = 128; off > 0; off >>= 1) {
                if (tid < off) red[tid] += red[tid + off];
                __syncthreads();
            }
            tot[t] = red[0];
            __syncthreads();
        }
        if (tid == 0) {
            float n_f  = sqrtf(tot[0]);
            float n_fo = sqrtf(tot[1]);
            float distil   = fabsf(n_f - n_fo);
            float res_loss = fabsf(sqrtf(tot[2]) - sqrtf(tot[3]));
            float res_inc  = fabsf(sqrtf(tot[4]) - n_f);
            out[OUT_DETS + 0] = distil;
            out[OUT_DETS + 1] = res_inc + res_loss;
        }
        return;
    }

    extern __shared__ unsigned char smraw[];
    unsigned* smask = (unsigned*)smraw;                 // [PADK*WMASK]
    float*    sx1   = (float*)(smask + PADK * WMASK);   // [PADK] x6
    float*    sy1   = sx1 + PADK;
    float*    sx2   = sy1 + PADK;
    float*    sy2   = sx2 + PADK;
    float*    sar   = sy2 + PADK;
    float*    ssc   = sar + PADK;
    float4*   sgt   = (float4*)(ssc + PADK);            // [N_GT]
    unsigned* sup   = (unsigned*)(sgt + N_GT);          // [64]
    __shared__ int sNum;

    const int lane = tid & 31;
    const int wid  = tid >> 5;
    const int cslot = blockIdx.x;
    const int Kv = g_Kv[cslot];
    const int W = (Kv + 31) >> 5;

    for (int a = 0; a < 6; a++) {
        const float4* s4 = (const float4*)&g_soa[a][cslot][0];
        float4* d4 = (float4*)(sx1 + (size_t)a * PADK);
        for (int i = tid; i < PADK / 4; i += 512) d4[i] = s4[i];
    }
    {   // mask copy (uint4 bulk, parallel)
        const uint4* s4 = (const uint4*)&g_mk[cslot][0][0];
        uint4* d4 = (uint4*)smask;
        const int n4 = (Kv * WMASK + 3) >> 2;
        for (int i = tid; i < n4; i += 512) d4[i] = s4[i];
    }
    if (tid < N_GT * 4)
        ((float*)sgt)[tid] = gt_boxes[(tid >> 2) * 5 + (tid & 3)];
    if (tid >= 128 && tid < 192) sup[tid - 128] = 0u;
    if (tid == 0) {
        int nb = num_boxes[0];
        sNum = nb < 0 ? 0 : (nb > N_GT ? N_GT : nb);
    }
    __syncthreads();

    if (Kv > 0) {
        // ---- branchless bit-serial greedy resolve (warp 0) ----
        if (wid == 0) {
            unsigned s_lo = 0u, s_hi = 0u;   // lane owns words lane, lane+32
            const int lastj = (Kv - 1) >> 5;
            const unsigned tailm = (Kv & 31) ? (~0u << (Kv & 31)) : 0u;
            for (int j = 0; j <= lastj; j++) {
                // broadcast loads: 32 diagonal words (row (j*32+b), word j);
                // every lane loads the same address -> conflict-free, off-chain
                const unsigned* diag = smask + (j << 5) * WMASK + j;
                unsigned d[32];
                #pragma unroll
                for (int b = 0; b < 32; b++) d[b] = diag[b * WMASK];

                unsigned wj = (j < 32) ? __shfl_sync(0xffffffffu, s_lo, j)
                                       : __shfl_sync(0xffffffffu, s_hi, j - 32);
                if (j == lastj) wj |= tailm;

                // 32-step branchless chain; d[b] has only bits > b, so ORing
                // never disturbs already-processed lower bits.
                unsigned keep = 0u;
                #pragma unroll
                for (int b = 0; b < 32; b++) {
                    unsigned supb = (unsigned)((int)(wj << (31 - b)) >> 31);
                    keep |= (~supb) & (1u << b);
                    wj |= d[b] & ~supb;
                }

                // deferred row ORs for kept boxes (warp-parallel, off-chain)
                unsigned t = keep;
                while (t) {
                    int b = __ffs(t) - 1; t &= t - 1;
                    const unsigned* row = smask + ((j << 5) + b) * WMASK;
                    if (lane >= j && lane < W) s_lo |= row[lane];
                    int l2 = lane + 32;
                    if (l2 >= j && l2 < W) s_hi |= row[l2];
                }
                if (j < 32) { if (lane == j) s_lo = wj; }
                else        { if (lane == j - 32) s_hi = wj; }
            }
            sup[lane] = s_lo;
            sup[32 + lane] = s_hi;
        }
        __syncthreads();

        // ---- GT dedup + output ----
        float* outc = out + (size_t)cslot * N_ROI * 5;
        const int numgt = sNum;
        for (int i = tid; i < Kv; i += 512) {
            if (!((sup[i >> 5] >> (i & 31)) & 1u)) {
                float bx1 = sx1[i], by1 = sy1[i], bx2 = sx2[i], by2 = sy2[i];
                float ba = sar[i];
                bool hit = false;
                for (int g = 0; g < numgt; g++) {
                    float4 c = sgt[g];
                    float areaB = (c.z - c.x) * (c.w - c.y);
                    float lx = fmaxf(bx1, c.x), ly = fmaxf(by1, c.y);
                    float rx = fminf(bx2, c.z), ry = fminf(by2, c.w);
                    float ww = fmaxf(rx - lx, 0.0f), hh = fmaxf(ry - ly, 0.0f);
                    float inter = ww * hh;
                    float iou = inter / (ba + areaB - inter + 1e-6f);
                    hit = hit || (iou > 0.3f);
                }
                if (!hit) {
                    outc[(size_t)i * 5 + 0] = bx1;
                    outc[(size_t)i * 5 + 1] = by1;
                    outc[(size_t)i * 5 + 2] = bx2;
                    outc[(size_t)i * 5 + 3] = by2;
                    outc[(size_t)i * 5 + 4] = ssc[i];
                }
            }
        }
    }
}

extern "C" void kernel_launch(void* const* d_in, const int* in_sizes, int n_in,
                              void* d_out, int out_size) {
    const float* rois      = (const float*)d_in[0];
    const float* cls_prob  = (const float*)d_in[1];
    const float* bbox_pred = (const float*)d_in[2];
    const float* im_info   = (const float*)d_in[3];
    const float* gt_boxes  = (const float*)d_in[4];
    const int*   num_boxes = (const int*)d_in[5];
    const float* feat      = (const float*)d_in[6];
    const float* feat_org  = (const float*)d_in[7];
    const float* feat_res  = (const float*)d_in[8];
    float* out = (float*)d_out;

    const int smem_res = (int)(PADK * WMASK * sizeof(unsigned)   // 165888
                             + 6 * PADK * sizeof(float)          //  27648
                             + N_GT * sizeof(float4)             //    320
                             + 64 * sizeof(unsigned));           //    256
    static int configured = 0;
    if (!configured) {
        cudaFuncSetAttribute(resolve_out,
                             cudaFuncAttributeMaxDynamicSharedMemorySize,
                             smem_res);
        configured = 1;
    }

    fused_pre<<<452, 256>>>(out, feat, feat_org, feat_res);
    rank_decode<<<dim3(8, 20), 256>>>(cls_prob, rois, bbox_pred, im_info);
    mask_build<<<dim3(16, 20), 256>>>();
    resolve_out<<<21, 512, smem_res>>>(gt_boxes, num_boxes, out);
}

// round 15
// speedup vs baseline: 3.2614x; 1.5720x over previous
#include <cuda_runtime.h>
#include <math.h>

#define N_ROI 2000
#define N_CLS 21
#define N_GT  20
#define N_PIX 1900
#define OUT_DETS (20 * N_ROI * 5)   // 200000
#define PADK 1152                   // padded sorted-box capacity
#define WMASK 36                    // PADK / 32 words per mask row
#define ROWS_PER_BLK 72             // PADK / 16 row tiles for mask_build
#define NGRP 32                     // channel groups (16 channels each)

// Global scratch (no allocations allowed)
__device__ float g_part[NGRP][3][N_PIX];
__device__ int   g_Kv[20];
__device__ __align__(16) float    g_soa[6][20][PADK];   // x1,y1,x2,y2,area,score
__device__ __align__(16) unsigned g_mk[20][PADK][WMASK];

// ---------------------------------------------------------------------------
// K1: fused prologue. Blocks 0-159: per-class rank+decode (8 blocks/class).
// Blocks 160-415: channel partial sums. Blocks 416-611: zero output.
// ---------------------------------------------------------------------------
__global__ void __launch_bounds__(256) pre_rank(
    float* __restrict__ out,
    const float* __restrict__ f, const float* __restrict__ fo,
    const float* __restrict__ fr,
    const float* __restrict__ cls_prob, const float* __restrict__ rois,
    const float* __restrict__ bbox_pred, const float* __restrict__ im_info)
{
    __shared__ unsigned long long keys[N_ROI];
    __shared__ __align__(16) unsigned long long ckeys[N_ROI + 2];
    __shared__ int cnt;
    const int tid = threadIdx.x;
    const int blk = blockIdx.x;

    if (blk >= 160) {
        const int b2 = blk - 160;
        if (b2 < 256) {
            int chunk = b2 & 7, g = b2 >> 3;       // g in [0,32)
            int p = chunk * 256 + tid;
            if (p >= N_PIX) return;
            const float* pf = f  + (size_t)g * 16 * N_PIX + p;
            const float* po = fo + (size_t)g * 16 * N_PIX + p;
            const float* pr = fr + (size_t)g * 16 * N_PIX + p;
            float s0 = 0.f, s1 = 0.f, s2 = 0.f;
            #pragma unroll 16
            for (int c = 0; c < 16; c++) {
                s0 += pf[(size_t)c * N_PIX];
                s1 += po[(size_t)c * N_PIX];
                s2 += pr[(size_t)c * N_PIX];
            }
            g_part[g][0][p] = s0;
            g_part[g][1][p] = s1;
            g_part[g][2][p] = s2;
        } else {
            int base = (b2 - 256) * 1024 + tid * 4;
            if (base + 3 < OUT_DETS + 2) {
                *(float4*)(out + base) = make_float4(0.f, 0.f, 0.f, 0.f);
            } else {
                for (int t = 0; t < 4; t++)
                    if (base + t < OUT_DETS + 2) out[base + t] = 0.0f;
            }
        }
        return;
    }

    // ---- rank + decode path (verified logic) ----
    const int cslot = blk >> 3;
    const int bx    = blk & 7;
    const int cls   = cslot + 1;

    if (tid == 0) cnt = 0;
    __syncthreads();

    for (int i = tid; i < N_ROI; i += 256) {
        float s = cls_prob[i * N_CLS + cls];
        unsigned long long k = (s > 0.5f)
            ? (((unsigned long long)__float_as_uint(s) << 32) |
               (unsigned)(0xFFFF - i))
            : 0ULL;
        keys[i] = k;
        if (k) ckeys[atomicAdd(&cnt, 1)] = k;
    }
    __syncthreads();
    const int Kv = cnt;
    if (tid == 0) {
        ckeys[Kv] = 0ULL;
        if (bx == 0) g_Kv[cslot] = (Kv < PADK) ? Kv : PADK;
    }
    __syncthreads();

    int j = bx * 256 + tid;
    if (j >= N_ROI) return;
    const unsigned long long kj = keys[j];
    if (kj == 0ULL) return;

    int rank = 0;
    const ulonglong2* ck2 = (const ulonglong2*)ckeys;
    const int n2 = (Kv + 1) >> 1;
    #pragma unroll 4
    for (int k = 0; k < n2; k++) {
        ulonglong2 a = ck2[k];
        rank += (a.x > kj) + (a.y > kj);
    }
    if (rank >= PADK) return;

    const float Hm1 = im_info[0] - 1.0f;
    const float Wm1 = im_info[1] - 1.0f;
    float x1 = rois[j * 5 + 1], y1 = rois[j * 5 + 2];
    float x2 = rois[j * 5 + 3], y2 = rois[j * 5 + 4];
    float w = x2 - x1 + 1.0f, h = y2 - y1 + 1.0f;
    float cx = x1 + 0.5f * w, cy = y1 + 0.5f * h;
    const float* d = bbox_pred + ((size_t)j * N_CLS + (size_t)cls) * 4;
    float dx = d[0] * 0.1f, dy = d[1] * 0.1f;
    float dw = d[2] * 0.2f, dh = d[3] * 0.2f;
    float pcx = dx * w + cx, pcy = dy * h + cy;
    float pw = expf(dw) * w, ph = expf(dh) * h;
    float px1 = fminf(fmaxf(pcx - 0.5f * pw, 0.0f), Wm1);
    float py1 = fminf(fmaxf(pcy - 0.5f * ph, 0.0f), Hm1);
    float px2 = fminf(fmaxf(pcx + 0.5f * pw, 0.0f), Wm1);
    float py2 = fminf(fmaxf(pcy + 0.5f * ph, 0.0f), Hm1);

    g_soa[0][cslot][rank] = px1;
    g_soa[1][cslot][rank] = py1;
    g_soa[2][cslot][rank] = px2;
    g_soa[3][cslot][rank] = py2;
    g_soa[4][cslot][rank] = (px2 - px1) * (py2 - py1);
    g_soa[5][cslot][rank] = __uint_as_float((unsigned)(kj >> 32));
}

// ---------------------------------------------------------------------------
// K2: pairwise suppression mask, full-chip. grid (16, 20), 256 threads.
// Division-free compare: iou > 0.3  <=>  inter > 0.3*denom (denom > 0),
// denom computed in the reference op order.
// ---------------------------------------------------------------------------
__global__ void __launch_bounds__(256) mask_build()
{
    __shared__ float sx1[PADK], sy1[PADK], sx2[PADK], sy2[PADK], sar[PADK];
    const int tid  = threadIdx.x;
    const int lane = tid & 31;
    const int wid  = tid >> 5;
    const int cslot = blockIdx.y;
    const int Kv = g_Kv[cslot];
    const int row0 = blockIdx.x * ROWS_PER_BLK;
    if (row0 >= Kv) return;
    const int rowend = (row0 + ROWS_PER_BLK < Kv) ? row0 + ROWS_PER_BLK : Kv;
    const int W = (Kv + 31) >> 5;

    for (int i = tid; i < PADK; i += 256) {
        sx1[i] = g_soa[0][cslot][i];
        sy1[i] = g_soa[1][cslot][i];
        sx2[i] = g_soa[2][cslot][i];
        sy2[i] = g_soa[3][cslot][i];
        sar[i] = g_soa[4][cslot][i];
    }
    __syncthreads();

    for (int row = row0 + wid; row < rowend; row += 8) {
        const int dw = row >> 5;
        const float bx1 = sx1[row], by1 = sy1[row];
        const float bx2 = sx2[row], by2 = sy2[row], ba = sar[row];
        for (int word = dw; word < W; word++) {
            int k = (word << 5) + lane;
            float lx = fmaxf(bx1, sx1[k]), ly = fmaxf(by1, sy1[k]);
            float rx = fminf(bx2, sx2[k]), ry = fminf(by2, sy2[k]);
            float ww = fmaxf(rx - lx, 0.0f), hh = fmaxf(ry - ly, 0.0f);
            float inter = ww * hh;
            float denom = (ba + sar[k] - inter) + 1e-6f;
            bool p = inter > 0.3f * denom;
            if (word == dw) p = p && (k > row);
            unsigned wbits = __ballot_sync(0xffffffffu, p);
            if (lane == 0) g_mk[cslot][row][word] = wbits;
        }
    }
}

// ---------------------------------------------------------------------------
// K3: per-class greedy resolve (predicated chain + dense pipelined row-OR)
// + GT dedup + output (blocks 0-19); block 20 does loss finalize.
// grid 21, 512 threads.
// ---------------------------------------------------------------------------
__global__ void __launch_bounds__(512) resolve_out(
    const float* __restrict__ gt_boxes, const int* __restrict__ num_boxes,
    float* __restrict__ out)
{
    const int tid = threadIdx.x;

    // ---- block 20: loss finalize ----
    if (blockIdx.x == 20) {
        __shared__ float red[256];
        if (tid >= 256) return;
        float a0 = 0.f, a1 = 0.f, a2 = 0.f, a3 = 0.f, a4 = 0.f;
        for (int p = tid; p < N_PIX; p += 256) {
            float mf = 0.f, mo = 0.f, mr = 0.f;
            #pragma unroll
            for (int g = 0; g < NGRP; g++) {
                mf += g_part[g][0][p];
                mo += g_part[g][1][p];
                mr += g_part[g][2][p];
            }
            mf *= (1.0f / 512.0f); mo *= (1.0f / 512.0f); mr *= (1.0f / 512.0f);
            a0 += mf * mf;
            a1 += mo * mo;
            float d = mf - mo; a2 += d * d;
            a3 += mr * mr;
            float s = mo + mr; a4 += s * s;
        }
        float acc[5] = {a0, a1, a2, a3, a4};
        float tot[5];
        for (int t = 0; t < 5; t++) {
            red[tid] = acc[t];
            __syncthreads();
            for (int off = 128; off > 0; off >>= 1) {
                if (tid < off) red[tid] += red[tid + off];
                __syncthreads();
            }
            tot[t] = red[0];
            __syncthreads();
        }
        if (tid == 0) {
            float n_f  = sqrtf(tot[0]);
            float n_fo = sqrtf(tot[1]);
            float distil   = fabsf(n_f - n_fo);
            float res_loss = fabsf(sqrtf(tot[2]) - sqrtf(tot[3]));
            float res_inc  = fabsf(sqrtf(tot[4]) - n_f);
            out[OUT_DETS + 0] = distil;
            out[OUT_DETS + 1] = res_inc + res_loss;
        }
        return;
    }

    extern __shared__ unsigned char smraw[];
    unsigned* smask = (unsigned*)smraw;                 // [PADK*WMASK]
    float*    sx1   = (float*)(smask + PADK * WMASK);   // [PADK] x6
    float*    sy1   = sx1 + PADK;
    float*    sx2   = sy1 + PADK;
    float*    sy2   = sx2 + PADK;
    float*    sar   = sy2 + PADK;
    float*    ssc   = sar + PADK;
    float4*   sgt   = (float4*)(ssc + PADK);            // [N_GT]
    unsigned* sup   = (unsigned*)(sgt + N_GT);          // [64]
    __shared__ int sNum;

    const int lane = tid & 31;
    const int wid  = tid >> 5;
    const int cslot = blockIdx.x;
    const int Kv = g_Kv[cslot];
    const int W = (Kv + 31) >> 5;

    for (int a = 0; a < 6; a++) {
        const float4* s4 = (const float4*)&g_soa[a][cslot][0];
        float4* d4 = (float4*)(sx1 + (size_t)a * PADK);
        for (int i = tid; i < PADK / 4; i += 512) d4[i] = s4[i];
    }
    {   // mask copy (uint4 bulk, parallel)
        const uint4* s4 = (const uint4*)&g_mk[cslot][0][0];
        uint4* d4 = (uint4*)smask;
        const int n4 = (Kv * WMASK + 3) >> 2;
        for (int i = tid; i < n4; i += 512) d4[i] = s4[i];
    }
    if (tid < N_GT * 4)
        ((float*)sgt)[tid] = gt_boxes[(tid >> 2) * 5 + (tid & 3)];
    if (tid >= 128 && tid < 192) sup[tid - 128] = 0u;
    if (tid == 0) {
        int nb = num_boxes[0];
        sNum = nb < 0 ? 0 : (nb > N_GT ? N_GT : nb);
    }
    __syncthreads();

    if (Kv > 0) {
        // ---- greedy resolve (warp 0) ----
        if (wid == 0) {
            unsigned s_lo = 0u, s_hi = 0u;   // lane owns words lane, lane+32
            const int lastj = (Kv - 1) >> 5;
            const unsigned tailm = (Kv & 31) ? (~0u << (Kv & 31)) : 0u;
            for (int j = 0; j <= lastj; j++) {
                const unsigned* base = smask + (j << 5) * WMASK;
                // broadcast diagonal loads (all lanes same addr, pipelined)
                unsigned d[32];
                #pragma unroll
                for (int b = 0; b < 32; b++) d[b] = base[b * WMASK + j];

                unsigned wj = (j < 32) ? __shfl_sync(0xffffffffu, s_lo, j)
                                       : __shfl_sync(0xffffffffu, s_hi, j - 32);
                if (j == lastj) wj |= tailm;

                // 32-step predicated chain (uniform across lanes);
                // d[b] has only bits > b, so ORing never disturbs lower bits.
                unsigned keep = 0u;
                #pragma unroll
                for (int b = 0; b < 32; b++) {
                    if (!(wj & (1u << b))) {
                        keep |= (1u << b);
                        wj |= d[b];
                    }
                }

                // dense pipelined row-OR: every lane loads all 32 rows' own
                // word (conflict-free, independent LDS) and masks by keep.
                if (lane >= j && lane < W) {
                    #pragma unroll
                    for (int b = 0; b < 32; b++) {
                        unsigned m = (unsigned)((int)(keep << (31 - b)) >> 31);
                        s_lo |= base[b * WMASK + lane] & m;
                    }
                }
                if (W > 32) {
                    int l2 = lane + 32;
                    if (l2 >= j && l2 < W) {
                        #pragma unroll
                        for (int b = 0; b < 32; b++) {
                            unsigned m = (unsigned)((int)(keep << (31 - b)) >> 31);
                            s_hi |= base[b * WMASK + l2] & m;
                        }
                    }
                }
                if (j < 32) { if (lane == j) s_lo = wj; }
                else        { if (lane == j - 32) s_hi = wj; }
            }
            sup[lane] = s_lo;
            sup[32 + lane] = s_hi;
        }
        __syncthreads();

        // ---- GT dedup + output (IEEE div kept, matches reference) ----
        float* outc = out + (size_t)cslot * N_ROI * 5;
        const int numgt = sNum;
        for (int i = tid; i < Kv; i += 512) {
            if (!((sup[i >> 5] >> (i & 31)) & 1u)) {
                float bx1 = sx1[i], by1 = sy1[i], bx2 = sx2[i], by2 = sy2[i];
                float ba = sar[i];
                bool hit = false;
                for (int g = 0; g < numgt; g++) {
                    float4 c = sgt[g];
                    float areaB = (c.z - c.x) * (c.w - c.y);
                    float lx = fmaxf(bx1, c.x), ly = fmaxf(by1, c.y);
                    float rx = fminf(bx2, c.z), ry = fminf(by2, c.w);
                    float ww = fmaxf(rx - lx, 0.0f), hh = fmaxf(ry - ly, 0.0f);
                    float inter = ww * hh;
                    float iou = inter / (ba + areaB - inter + 1e-6f);
                    hit = hit || (iou > 0.3f);
                }
                if (!hit) {
                    outc[(size_t)i * 5 + 0] = bx1;
                    outc[(size_t)i * 5 + 1] = by1;
                    outc[(size_t)i * 5 + 2] = bx2;
                    outc[(size_t)i * 5 + 3] = by2;
                    outc[(size_t)i * 5 + 4] = ssc[i];
                }
            }
        }
    }
}

extern "C" void kernel_launch(void* const* d_in, const int* in_sizes, int n_in,
                              void* d_out, int out_size) {
    const float* rois      = (const float*)d_in[0];
    const float* cls_prob  = (const float*)d_in[1];
    const float* bbox_pred = (const float*)d_in[2];
    const float* im_info   = (const float*)d_in[3];
    const float* gt_boxes  = (const float*)d_in[4];
    const int*   num_boxes = (const int*)d_in[5];
    const float* feat      = (const float*)d_in[6];
    const float* feat_org  = (const float*)d_in[7];
    const float* feat_res  = (const float*)d_in[8];
    float* out = (float*)d_out;

    const int smem_res = (int)(PADK * WMASK * sizeof(unsigned)   // 165888
                             + 6 * PADK * sizeof(float)          //  27648
                             + N_GT * sizeof(float4)             //    320
                             + 64 * sizeof(unsigned));           //    256
    static int configured = 0;
    if (!configured) {
        cudaFuncSetAttribute(resolve_out,
                             cudaFuncAttributeMaxDynamicSharedMemorySize,
                             smem_res);
        configured = 1;
    }

    pre_rank<<<612, 256>>>(out, feat, feat_org, feat_res,
                           cls_prob, rois, bbox_pred, im_info);
    mask_build<<<dim3(16, 20), 256>>>();
    resolve_out<<<21, 512, smem_res>>>(gt_boxes, num_boxes, out);
}

// round 16
// speedup vs baseline: 3.9464x; 1.2101x over previous
#include <cuda_runtime.h>
#include <math.h>

#define N_ROI 2000
#define N_CLS 21
#define N_GT  20
#define N_PIX 1900
#define OUT_DETS (20 * N_ROI * 5)   // 200000
#define PADK 1152                   // padded sorted-box capacity
#define WMASK 36                    // PADK / 32 words per mask row
#define ROWS_PER_BLK 72             // PADK / 16 row tiles for mask_build
#define NGRP 32                     // channel groups (16 channels each)
#define NBKT 4096                   // rank buckets (top-12 mantissa bits)

// Global scratch (no allocations allowed)
__device__ float g_part[NGRP][3][N_PIX];
__device__ int   g_Kv[20];
__device__ __align__(16) float    g_soa[6][20][PADK];   // x1,y1,x2,y2,area,score
__device__ __align__(16) unsigned g_mk[20][PADK][WMASK];

// ---------------------------------------------------------------------------
// K1: fused prologue, 512-thread blocks.
//   blocks [0,20):    per-class O(N) bucket-rank + decode + scatter
//   blocks [20,139):  channel partial sums (32 groups x 1900 pixels)
//   blocks [139,237): zero output
// ---------------------------------------------------------------------------
__global__ void __launch_bounds__(512) pre_rank(
    float* __restrict__ out,
    const float* __restrict__ f, const float* __restrict__ fo,
    const float* __restrict__ fr,
    const float* __restrict__ cls_prob, const float* __restrict__ rois,
    const float* __restrict__ bbox_pred, const float* __restrict__ im_info)
{
    __shared__ unsigned hist[NBKT + 1];
    __shared__ unsigned long long sk2[2048];
    __shared__ unsigned wtot[16];

    const int tid = threadIdx.x;
    const int blk = blockIdx.x;

    if (blk >= 20) {
        if (blk < 139) {
            // ---- channel partial sums ----
            int id = (blk - 20) * 512 + tid;
            if (id >= NGRP * N_PIX) return;
            int g = id / N_PIX;
            int p = id - g * N_PIX;
            const float* pf = f  + (size_t)g * 16 * N_PIX + p;
            const float* po = fo + (size_t)g * 16 * N_PIX + p;
            const float* pr = fr + (size_t)g * 16 * N_PIX + p;
            float s0 = 0.f, s1 = 0.f, s2 = 0.f;
            #pragma unroll 16
            for (int c = 0; c < 16; c++) {
                s0 += pf[(size_t)c * N_PIX];
                s1 += po[(size_t)c * N_PIX];
                s2 += pr[(size_t)c * N_PIX];
            }
            g_part[g][0][p] = s0;
            g_part[g][1][p] = s1;
            g_part[g][2][p] = s2;
        } else {
            // ---- zero output ----
            int i = (blk - 139) * 512 + tid;        // float4 index
            if (i < 50000) {
                ((float4*)out)[i] = make_float4(0.f, 0.f, 0.f, 0.f);
            } else if (i == 50000) {
                out[200000] = 0.0f;
                out[200001] = 0.0f;
            }
        }
        return;
    }

    // =========================== rank + decode ===========================
    const int cslot = blk;
    const int cls   = cslot + 1;
    const int lane  = tid & 31;
    const int wrp   = tid >> 5;

    for (int i = tid; i < NBKT + 1; i += 512) hist[i] = 0u;
    __syncthreads();

    // ---- Phase A: keys, buckets, arrival counters (4 rois/thread) ----
    unsigned long long key[4];
    int bkt[4], arr[4];
    #pragma unroll
    for (int s = 0; s < 4; s++) {
        int j = tid + s * 512;
        key[s] = 0ULL;
        bkt[s] = -1;
        if (j < N_ROI) {
            float sc = cls_prob[j * N_CLS + cls];
            if (sc > 0.5f) {
                unsigned sb = __float_as_uint(sc);
                key[s] = ((unsigned long long)sb << 32) |
                         (unsigned)(0xFFFF - j);
                // monotone clamped bucket: valid scores are in (0.5,1) so
                // sb>>11 - (0x3F000000>>11) is the top-12 mantissa bits;
                // clamp keeps it monotone for any positive float.
                int t = (int)(sb >> 11) - (int)(0x3F000000u >> 11);
                t = t < 0 ? 0 : (t > (NBKT - 1) ? (NBKT - 1) : t);
                bkt[s] = (NBKT - 1) - t;            // descending score
                arr[s] = (int)atomicAdd(&hist[bkt[s]], 1u);
            }
        }
    }
    __syncthreads();

    // ---- Phase B: exclusive block scan of hist[0..4095] (8/thread) ----
    unsigned loc[8];
    unsigned tsum = 0;
    const int base = tid * 8;
    #pragma unroll
    for (int t = 0; t < 8; t++) { loc[t] = hist[base + t]; tsum += loc[t]; }
    unsigned x = tsum;
    #pragma unroll
    for (int o = 1; o < 32; o <<= 1) {
        unsigned y = __shfl_up_sync(0xffffffffu, x, o);
        if (lane >= o) x += y;
    }
    if (lane == 31) wtot[wrp] = x;                  // warp inclusive totals
    __syncthreads();
    if (wrp == 0) {
        unsigned v = (lane < 16) ? wtot[lane] : 0u;
        unsigned orig = v;
        #pragma unroll
        for (int o = 1; o < 16; o <<= 1) {
            unsigned y = __shfl_up_sync(0xffffffffu, v, o);
            if (lane >= o) v += y;
        }
        if (lane < 16) wtot[lane] = v - orig;       // warp exclusive offsets
    }
    __syncthreads();
    unsigned run = wtot[wrp] + (x - tsum);          // thread exclusive offset
    #pragma unroll
    for (int t = 0; t < 8; t++) { hist[base + t] = run; run += loc[t]; }
    if (tid == 511) hist[NBKT] = run;               // grand total = Kv
    __syncthreads();

    const int Kv = (int)hist[NBKT];
    if (tid == 0) g_Kv[cslot] = (Kv < PADK) ? Kv : PADK;

    // ---- Phase C: scatter keys by slot ----
    #pragma unroll
    for (int s = 0; s < 4; s++) {
        if (bkt[s] >= 0) {
            unsigned slot = hist[bkt[s]] + (unsigned)arr[s];
            sk2[slot] = key[s];
        }
    }
    __syncthreads();

    // ---- Phase D: final rank (+ tie fix) + decode + scatter ----
    const float Hm1 = im_info[0] - 1.0f;
    const float Wm1 = im_info[1] - 1.0f;
    #pragma unroll
    for (int s = 0; s < 4; s++) {
        if (bkt[s] < 0) continue;
        const unsigned o0 = hist[bkt[s]];
        const unsigned o1 = hist[bkt[s] + 1];
        int rank = (int)o0;
        if (o1 - o0 > 1u) {                         // rare: bucket collision
            for (unsigned q = o0; q < o1; q++)
                rank += (sk2[q] > key[s]);
        }
        if (rank >= PADK) continue;

        const int j = tid + s * 512;
        float x1 = rois[j * 5 + 1], y1 = rois[j * 5 + 2];
        float x2 = rois[j * 5 + 3], y2 = rois[j * 5 + 4];
        float w = x2 - x1 + 1.0f, h = y2 - y1 + 1.0f;
        float cx = x1 + 0.5f * w, cy = y1 + 0.5f * h;
        const float* d = bbox_pred + ((size_t)j * N_CLS + (size_t)cls) * 4;
        float dx = d[0] * 0.1f, dy = d[1] * 0.1f;
        float dw = d[2] * 0.2f, dh = d[3] * 0.2f;
        float pcx = dx * w + cx, pcy = dy * h + cy;
        float pw = expf(dw) * w, ph = expf(dh) * h;
        float px1 = fminf(fmaxf(pcx - 0.5f * pw, 0.0f), Wm1);
        float py1 = fminf(fmaxf(pcy - 0.5f * ph, 0.0f), Hm1);
        float px2 = fminf(fmaxf(pcx + 0.5f * pw, 0.0f), Wm1);
        float py2 = fminf(fmaxf(pcy + 0.5f * ph, 0.0f), Hm1);

        g_soa[0][cslot][rank] = px1;
        g_soa[1][cslot][rank] = py1;
        g_soa[2][cslot][rank] = px2;
        g_soa[3][cslot][rank] = py2;
        g_soa[4][cslot][rank] = (px2 - px1) * (py2 - py1);
        g_soa[5][cslot][rank] = __uint_as_float((unsigned)(key[s] >> 32));
    }
}

// ---------------------------------------------------------------------------
// K2: pairwise suppression mask, full-chip. grid (16, 20), 256 threads.
// Division-free compare (verified): iou > 0.3 <=> inter > 0.3*denom.
// ---------------------------------------------------------------------------
__global__ void __launch_bounds__(256) mask_build()
{
    __shared__ float sx1[PADK], sy1[PADK], sx2[PADK], sy2[PADK], sar[PADK];
    const int tid  = threadIdx.x;
    const int lane = tid & 31;
    const int wid  = tid >> 5;
    const int cslot = blockIdx.y;
    const int Kv = g_Kv[cslot];
    const int row0 = blockIdx.x * ROWS_PER_BLK;
    if (row0 >= Kv) return;
    const int rowend = (row0 + ROWS_PER_BLK < Kv) ? row0 + ROWS_PER_BLK : Kv;
    const int W = (Kv + 31) >> 5;

    for (int i = tid; i < PADK; i += 256) {
        sx1[i] = g_soa[0][cslot][i];
        sy1[i] = g_soa[1][cslot][i];
        sx2[i] = g_soa[2][cslot][i];
        sy2[i] = g_soa[3][cslot][i];
        sar[i] = g_soa[4][cslot][i];
    }
    __syncthreads();

    for (int row = row0 + wid; row < rowend; row += 8) {
        const int dw = row >> 5;
        const float bx1 = sx1[row], by1 = sy1[row];
        const float bx2 = sx2[row], by2 = sy2[row], ba = sar[row];
        for (int word = dw; word < W; word++) {
            int k = (word << 5) + lane;
            float lx = fmaxf(bx1, sx1[k]), ly = fmaxf(by1, sy1[k]);
            float rx = fminf(bx2, sx2[k]), ry = fminf(by2, sy2[k]);
            float ww = fmaxf(rx - lx, 0.0f), hh = fmaxf(ry - ly, 0.0f);
            float inter = ww * hh;
            float denom = (ba + sar[k] - inter) + 1e-6f;
            bool p = inter > 0.3f * denom;
            if (word == dw) p = p && (k > row);
            unsigned wbits = __ballot_sync(0xffffffffu, p);
            if (lane == 0) g_mk[cslot][row][word] = wbits;
        }
    }
}

// ---------------------------------------------------------------------------
// K3: per-class greedy resolve (predicated chain + dense pipelined row-OR)
// + GT dedup + output (blocks 0-19); block 20 does loss finalize.
// grid 21, 512 threads. (verified)
// ---------------------------------------------------------------------------
__global__ void __launch_bounds__(512) resolve_out(
    const float* __restrict__ gt_boxes, const int* __restrict__ num_boxes,
    float* __restrict__ out)
{
    const int tid = threadIdx.x;

    // ---- block 20: loss finalize ----
    if (blockIdx.x == 20) {
        __shared__ float red[256];
        if (tid >= 256) return;
        float a0 = 0.f, a1 = 0.f, a2 = 0.f, a3 = 0.f, a4 = 0.f;
        for (int p = tid; p < N_PIX; p += 256) {
            float mf = 0.f, mo = 0.f, mr = 0.f;
            #pragma unroll
            for (int g = 0; g < NGRP; g++) {
                mf += g_part[g][0][p];
                mo += g_part[g][1][p];
                mr += g_part[g][2][p];
            }
            mf *= (1.0f / 512.0f); mo *= (1.0f / 512.0f); mr *= (1.0f / 512.0f);
            a0 += mf * mf;
            a1 += mo * mo;
            float d = mf - mo; a2 += d * d;
            a3 += mr * mr;
            float s = mo + mr; a4 += s * s;
        }
        float acc[5] = {a0, a1, a2, a3, a4};
        float tot[5];
        for (int t = 0; t < 5; t++) {
            red[tid] = acc[t];
            __syncthreads();
            for (int off = 128; off > 0; off >>= 1) {
                if (tid < off) red[tid] += red[tid + off];
                __syncthreads();
            }
            tot[t] = red[0];
            __syncthreads();
        }
        if (tid == 0) {
            float n_f  = sqrtf(tot[0]);
            float n_fo = sqrtf(tot[1]);
            float distil   = fabsf(n_f - n_fo);
            float res_loss = fabsf(sqrtf(tot[2]) - sqrtf(tot[3]));
            float res_inc  = fabsf(sqrtf(tot[4]) - n_f);
            out[OUT_DETS + 0] = distil;
            out[OUT_DETS + 1] = res_inc + res_loss;
        }
        return;
    }

    extern __shared__ unsigned char smraw[];
    unsigned* smask = (unsigned*)smraw;                 // [PADK*WMASK]
    float*    sx1   = (float*)(smask + PADK * WMASK);   // [PADK] x6
    float*    sy1   = sx1 + PADK;
    float*    sx2   = sy1 + PADK;
    float*    sy2   = sx2 + PADK;
    float*    sar   = sy2 + PADK;
    float*    ssc   = sar + PADK;
    float4*   sgt   = (float4*)(ssc + PADK);            // [N_GT]
    unsigned* sup   = (unsigned*)(sgt + N_GT);          // [64]
    __shared__ int sNum;

    const int lane = tid & 31;
    const int wid  = tid >> 5;
    const int cslot = blockIdx.x;
    const int Kv = g_Kv[cslot];
    const int W = (Kv + 31) >> 5;

    for (int a = 0; a < 6; a++) {
        const float4* s4 = (const float4*)&g_soa[a][cslot][0];
        float4* d4 = (float4*)(sx1 + (size_t)a * PADK);
        for (int i = tid; i < PADK / 4; i += 512) d4[i] = s4[i];
    }
    {   // mask copy (uint4 bulk, parallel)
        const uint4* s4 = (const uint4*)&g_mk[cslot][0][0];
        uint4* d4 = (uint4*)smask;
        const int n4 = (Kv * WMASK + 3) >> 2;
        for (int i = tid; i < n4; i += 512) d4[i] = s4[i];
    }
    if (tid < N_GT * 4)
        ((float*)sgt)[tid] = gt_boxes[(tid >> 2) * 5 + (tid & 3)];
    if (tid >= 128 && tid < 192) sup[tid - 128] = 0u;
    if (tid == 0) {
        int nb = num_boxes[0];
        sNum = nb < 0 ? 0 : (nb > N_GT ? N_GT : nb);
    }
    __syncthreads();

    if (Kv > 0) {
        // ---- greedy resolve (warp 0) ----
        if (wid == 0) {
            unsigned s_lo = 0u, s_hi = 0u;   // lane owns words lane, lane+32
            const int lastj = (Kv - 1) >> 5;
            const unsigned tailm = (Kv & 31) ? (~0u << (Kv & 31)) : 0u;
            for (int j = 0; j <= lastj; j++) {
                const unsigned* base = smask + (j << 5) * WMASK;
                unsigned d[32];
                #pragma unroll
                for (int b = 0; b < 32; b++) d[b] = base[b * WMASK + j];

                unsigned wj = (j < 32) ? __shfl_sync(0xffffffffu, s_lo, j)
                                       : __shfl_sync(0xffffffffu, s_hi, j - 32);
                if (j == lastj) wj |= tailm;

                unsigned keep = 0u;
                #pragma unroll
                for (int b = 0; b < 32; b++) {
                    if (!(wj & (1u << b))) {
                        keep |= (1u << b);
                        wj |= d[b];
                    }
                }

                if (lane >= j && lane < W) {
                    #pragma unroll
                    for (int b = 0; b < 32; b++) {
                        unsigned m = (unsigned)((int)(keep << (31 - b)) >> 31);
                        s_lo |= base[b * WMASK + lane] & m;
                    }
                }
                if (W > 32) {
                    int l2 = lane + 32;
                    if (l2 >= j && l2 < W) {
                        #pragma unroll
                        for (int b = 0; b < 32; b++) {
                            unsigned m = (unsigned)((int)(keep << (31 - b)) >> 31);
                            s_hi |= base[b * WMASK + l2] & m;
                        }
                    }
                }
                if (j < 32) { if (lane == j) s_lo = wj; }
                else        { if (lane == j - 32) s_hi = wj; }
            }
            sup[lane] = s_lo;
            sup[32 + lane] = s_hi;
        }
        __syncthreads();

        // ---- GT dedup + output (IEEE div kept, matches reference) ----
        float* outc = out + (size_t)cslot * N_ROI * 5;
        const int numgt = sNum;
        for (int i = tid; i < Kv; i += 512) {
            if (!((sup[i >> 5] >> (i & 31)) & 1u)) {
                float bx1 = sx1[i], by1 = sy1[i], bx2 = sx2[i], by2 = sy2[i];
                float ba = sar[i];
                bool hit = false;
                for (int g = 0; g < numgt; g++) {
                    float4 c = sgt[g];
                    float areaB = (c.z - c.x) * (c.w - c.y);
                    float lx = fmaxf(bx1, c.x), ly = fmaxf(by1, c.y);
                    float rx = fminf(bx2, c.z), ry = fminf(by2, c.w);
                    float ww = fmaxf(rx - lx, 0.0f), hh = fmaxf(ry - ly, 0.0f);
                    float inter = ww * hh;
                    float iou = inter / (ba + areaB - inter + 1e-6f);
                    hit = hit || (iou > 0.3f);
                }
                if (!hit) {
                    outc[(size_t)i * 5 + 0] = bx1;
                    outc[(size_t)i * 5 + 1] = by1;
                    outc[(size_t)i * 5 + 2] = bx2;
                    outc[(size_t)i * 5 + 3] = by2;
                    outc[(size_t)i * 5 + 4] = ssc[i];
                }
            }
        }
    }
}

extern "C" void kernel_launch(void* const* d_in, const int* in_sizes, int n_in,
                              void* d_out, int out_size) {
    const float* rois      = (const float*)d_in[0];
    const float* cls_prob  = (const float*)d_in[1];
    const float* bbox_pred = (const float*)d_in[2];
    const float* im_info   = (const float*)d_in[3];
    const float* gt_boxes  = (const float*)d_in[4];
    const int*   num_boxes = (const int*)d_in[5];
    const float* feat      = (const float*)d_in[6];
    const float* feat_org  = (const float*)d_in[7];
    const float* feat_res  = (const float*)d_in[8];
    float* out = (float*)d_out;

    const int smem_res = (int)(PADK * WMASK * sizeof(unsigned)   // 165888
                             + 6 * PADK * sizeof(float)          //  27648
                             + N_GT * sizeof(float4)             //    320
                             + 64 * sizeof(unsigned));           //    256
    static int configured = 0;
    if (!configured) {
        cudaFuncSetAttribute(resolve_out,
                             cudaFuncAttributeMaxDynamicSharedMemorySize,
                             smem_res);
        configured = 1;
    }

    pre_rank<<<237, 512>>>(out, feat, feat_org, feat_res,
                           cls_prob, rois, bbox_pred, im_info);
    mask_build<<<dim3(16, 20), 256>>>();
    resolve_out<<<21, 512, smem_res>>>(gt_boxes, num_boxes, out);
}

// round 17
// speedup vs baseline: 3.9557x; 1.0024x over previous
#include <cuda_runtime.h>
#include <math.h>

#define N_ROI 2000
#define N_CLS 21
#define N_GT  20
#define N_PIX 1900
#define OUT_DETS (20 * N_ROI * 5)   // 200000
#define PADK 1152                   // padded sorted-box capacity
#define WMASK 36                    // PADK / 32 words per mask row
#define ROWS_PER_BLK 72             // PADK / 16 row tiles for mask
#define NGRP 32                     // channel groups (16 channels each)
#define NBKT 4096                   // rank buckets (top-12 mantissa bits)

// Global scratch (no allocations allowed)
__device__ float g_part[NGRP][3][N_PIX];
__device__ int   g_Kv[20];
__device__ int   g_rank_done[20];   // set by K1 rank blocks, reset by K2
__device__ __align__(16) float    g_soa[6][20][PADK];   // x1,y1,x2,y2,area,score
__device__ __align__(16) unsigned g_mk[20][PADK][WMASK];

// ---------------------------------------------------------------------------
// K1: fused rank + channel-sums + mask with per-class flag handshake.
//   blocks [0,20):    per-class O(N) bucket-rank + decode + scatter -> flag
//   blocks [20,139):  channel partial sums
//   blocks [139,459): mask build (16 blocks/class), spin on class flag
// 459 blocks x 512 thr x ~33KB static smem -> 4 blocks/SM -> all resident
// in wave 1 (capacity 592), so the spin can never deadlock.
// ---------------------------------------------------------------------------
__global__ void __launch_bounds__(512) k1_fused(
    const float* __restrict__ f, const float* __restrict__ fo,
    const float* __restrict__ fr,
    const float* __restrict__ cls_prob, const float* __restrict__ rois,
    const float* __restrict__ bbox_pred, const float* __restrict__ im_info)
{
    __shared__ __align__(16) unsigned char sh[32896];
    const int tid = threadIdx.x;
    const int blk = blockIdx.x;
    const int lane = tid & 31;
    const int wrp  = tid >> 5;

    if (blk >= 20 && blk < 139) {
        // ---- channel partial sums (verified) ----
        int id = (blk - 20) * 512 + tid;
        if (id >= NGRP * N_PIX) return;
        int g = id / N_PIX;
        int p = id - g * N_PIX;
        const float* pf = f  + (size_t)g * 16 * N_PIX + p;
        const float* po = fo + (size_t)g * 16 * N_PIX + p;
        const float* pr = fr + (size_t)g * 16 * N_PIX + p;
        float s0 = 0.f, s1 = 0.f, s2 = 0.f;
        #pragma unroll 16
        for (int c = 0; c < 16; c++) {
            s0 += pf[(size_t)c * N_PIX];
            s1 += po[(size_t)c * N_PIX];
            s2 += pr[(size_t)c * N_PIX];
        }
        g_part[g][0][p] = s0;
        g_part[g][1][p] = s1;
        g_part[g][2][p] = s2;
        return;
    }

    if (blk < 20) {
        // ================= rank + decode (verified R15 logic) =================
        unsigned long long* sk2 = (unsigned long long*)sh;          // 16384 B
        unsigned* hist = (unsigned*)(sh + 16384);                   // 16388 B
        unsigned* wtot = (unsigned*)(sh + 16384 + 16400);           //    64 B

        const int cslot = blk;
        const int cls   = cslot + 1;

        for (int i = tid; i < NBKT + 1; i += 512) hist[i] = 0u;
        __syncthreads();

        unsigned long long key[4];
        int bkt[4], arr[4];
        #pragma unroll
        for (int s = 0; s < 4; s++) {
            int j = tid + s * 512;
            key[s] = 0ULL;
            bkt[s] = -1;
            if (j < N_ROI) {
                float sc = cls_prob[j * N_CLS + cls];
                if (sc > 0.5f) {
                    unsigned sb = __float_as_uint(sc);
                    key[s] = ((unsigned long long)sb << 32) |
                             (unsigned)(0xFFFF - j);
                    int t = (int)(sb >> 11) - (int)(0x3F000000u >> 11);
                    t = t < 0 ? 0 : (t > (NBKT - 1) ? (NBKT - 1) : t);
                    bkt[s] = (NBKT - 1) - t;
                    arr[s] = (int)atomicAdd(&hist[bkt[s]], 1u);
                }
            }
        }
        __syncthreads();

        // exclusive block scan of hist (8/thread)
        unsigned loc[8];
        unsigned tsum = 0;
        const int base = tid * 8;
        #pragma unroll
        for (int t = 0; t < 8; t++) { loc[t] = hist[base + t]; tsum += loc[t]; }
        unsigned x = tsum;
        #pragma unroll
        for (int o = 1; o < 32; o <<= 1) {
            unsigned y = __shfl_up_sync(0xffffffffu, x, o);
            if (lane >= o) x += y;
        }
        if (lane == 31) wtot[wrp] = x;
        __syncthreads();
        if (wrp == 0) {
            unsigned v = (lane < 16) ? wtot[lane] : 0u;
            unsigned orig = v;
            #pragma unroll
            for (int o = 1; o < 16; o <<= 1) {
                unsigned y = __shfl_up_sync(0xffffffffu, v, o);
                if (lane >= o) v += y;
            }
            if (lane < 16) wtot[lane] = v - orig;
        }
        __syncthreads();
        unsigned run = wtot[wrp] + (x - tsum);
        #pragma unroll
        for (int t = 0; t < 8; t++) { hist[base + t] = run; run += loc[t]; }
        if (tid == 511) hist[NBKT] = run;
        __syncthreads();

        const int Kv = (int)hist[NBKT];
        if (tid == 0) g_Kv[cslot] = (Kv < PADK) ? Kv : PADK;

        #pragma unroll
        for (int s = 0; s < 4; s++) {
            if (bkt[s] >= 0) {
                unsigned slot = hist[bkt[s]] + (unsigned)arr[s];
                sk2[slot] = key[s];
            }
        }
        __syncthreads();

        const float Hm1 = im_info[0] - 1.0f;
        const float Wm1 = im_info[1] - 1.0f;
        #pragma unroll
        for (int s = 0; s < 4; s++) {
            if (bkt[s] < 0) continue;
            const unsigned o0 = hist[bkt[s]];
            const unsigned o1 = hist[bkt[s] + 1];
            int rank = (int)o0;
            if (o1 - o0 > 1u) {
                for (unsigned q = o0; q < o1; q++)
                    rank += (sk2[q] > key[s]);
            }
            if (rank >= PADK) continue;

            const int j = tid + s * 512;
            float x1 = rois[j * 5 + 1], y1 = rois[j * 5 + 2];
            float x2 = rois[j * 5 + 3], y2 = rois[j * 5 + 4];
            float w = x2 - x1 + 1.0f, h = y2 - y1 + 1.0f;
            float cx = x1 + 0.5f * w, cy = y1 + 0.5f * h;
            const float* d = bbox_pred + ((size_t)j * N_CLS + (size_t)cls) * 4;
            float dx = d[0] * 0.1f, dy = d[1] * 0.1f;
            float dw = d[2] * 0.2f, dh = d[3] * 0.2f;
            float pcx = dx * w + cx, pcy = dy * h + cy;
            float pw = expf(dw) * w, ph = expf(dh) * h;
            float px1 = fminf(fmaxf(pcx - 0.5f * pw, 0.0f), Wm1);
            float py1 = fminf(fmaxf(pcy - 0.5f * ph, 0.0f), Hm1);
            float px2 = fminf(fmaxf(pcx + 0.5f * pw, 0.0f), Wm1);
            float py2 = fminf(fmaxf(pcy + 0.5f * ph, 0.0f), Hm1);

            g_soa[0][cslot][rank] = px1;
            g_soa[1][cslot][rank] = py1;
            g_soa[2][cslot][rank] = px2;
            g_soa[3][cslot][rank] = py2;
            g_soa[4][cslot][rank] = (px2 - px1) * (py2 - py1);
            g_soa[5][cslot][rank] = __uint_as_float((unsigned)(key[s] >> 32));
        }

        // publish: all writes fenced, then release the class flag
        __threadfence();
        __syncthreads();
        if (tid == 0) atomicExch(&g_rank_done[cslot], 1);
        return;
    }

    // ====================== mask build (spin on flag) ======================
    {
        float* sx1 = (float*)sh;
        float* sy1 = sx1 + PADK;
        float* sx2 = sy1 + PADK;
        float* sy2 = sx2 + PADK;
        float* sar = sy2 + PADK;

        const int m = blk - 139;
        const int cslot = m >> 4;
        const int tile  = m & 15;
        const int wid   = tid >> 5;

        if (tid == 0) {
            while (atomicAdd(&g_rank_done[cslot], 0) == 0) {}
            __threadfence();   // acquire: order flag observation before reads
        }
        __syncthreads();

        const int Kv = g_Kv[cslot];
        const int row0 = tile * ROWS_PER_BLK;
        if (row0 >= Kv) return;
        const int rowend = (row0 + ROWS_PER_BLK < Kv) ? row0 + ROWS_PER_BLK : Kv;
        const int W = (Kv + 31) >> 5;

        for (int i = tid; i < PADK; i += 512) {
            sx1[i] = g_soa[0][cslot][i];
            sy1[i] = g_soa[1][cslot][i];
            sx2[i] = g_soa[2][cslot][i];
            sy2[i] = g_soa[3][cslot][i];
            sar[i] = g_soa[4][cslot][i];
        }
        __syncthreads();

        for (int row = row0 + wid; row < rowend; row += 16) {
            const int dw = row >> 5;
            const float bx1 = sx1[row], by1 = sy1[row];
            const float bx2 = sx2[row], by2 = sy2[row], ba = sar[row];
            for (int word = dw; word < W; word++) {
                int k = (word << 5) + lane;
                float lx = fmaxf(bx1, sx1[k]), ly = fmaxf(by1, sy1[k]);
                float rx = fminf(bx2, sx2[k]), ry = fminf(by2, sy2[k]);
                float ww = fmaxf(rx - lx, 0.0f), hh = fmaxf(ry - ly, 0.0f);
                float inter = ww * hh;
                float denom = (ba + sar[k] - inter) + 1e-6f;
                bool p = inter > 0.3f * denom;
                if (word == dw) p = p && (k > row);
                unsigned wbits = __ballot_sync(0xffffffffu, p);
                if (lane == 0) g_mk[cslot][row][word] = wbits;
            }
        }
    }
}

// ---------------------------------------------------------------------------
// K2: per-class greedy resolve (verified) + det-slice zero + GT dedup +
// output (blocks 0-19); block 20 does loss finalize. grid 21, 512 threads.
// Also resets g_rank_done for the next graph replay.
// ---------------------------------------------------------------------------
__global__ void __launch_bounds__(512) resolve_out(
    const float* __restrict__ gt_boxes, const int* __restrict__ num_boxes,
    float* __restrict__ out)
{
    const int tid = threadIdx.x;

    // ---- block 20: loss finalize ----
    if (blockIdx.x == 20) {
        __shared__ float red[256];
        if (tid >= 256) return;
        float a0 = 0.f, a1 = 0.f, a2 = 0.f, a3 = 0.f, a4 = 0.f;
        for (int p = tid; p < N_PIX; p += 256) {
            float mf = 0.f, mo = 0.f, mr = 0.f;
            #pragma unroll
            for (int g = 0; g < NGRP; g++) {
                mf += g_part[g][0][p];
                mo += g_part[g][1][p];
                mr += g_part[g][2][p];
            }
            mf *= (1.0f / 512.0f); mo *= (1.0f / 512.0f); mr *= (1.0f / 512.0f);
            a0 += mf * mf;
            a1 += mo * mo;
            float d = mf - mo; a2 += d * d;
            a3 += mr * mr;
            float s = mo + mr; a4 += s * s;
        }
        float acc[5] = {a0, a1, a2, a3, a4};
        float tot[5];
        for (int t = 0; t < 5; t++) {
            red[tid] = acc[t];
            __syncthreads();
            for (int off = 128; off > 0; off >>= 1) {
                if (tid < off) red[tid] += red[tid + off];
                __syncthreads();
            }
            tot[t] = red[0];
            __syncthreads();
        }
        if (tid == 0) {
            float n_f  = sqrtf(tot[0]);
            float n_fo = sqrtf(tot[1]);
            float distil   = fabsf(n_f - n_fo);
            float res_loss = fabsf(sqrtf(tot[2]) - sqrtf(tot[3]));
            float res_inc  = fabsf(sqrtf(tot[4]) - n_f);
            out[OUT_DETS + 0] = distil;
            out[OUT_DETS + 1] = res_inc + res_loss;
        }
        return;
    }

    extern __shared__ unsigned char smraw[];
    unsigned* smask = (unsigned*)smraw;                 // [PADK*WMASK]
    float*    sx1   = (float*)(smask + PADK * WMASK);   // [PADK] x6
    float*    sy1   = sx1 + PADK;
    float*    sx2   = sy1 + PADK;
    float*    sy2   = sx2 + PADK;
    float*    sar   = sy2 + PADK;
    float*    ssc   = sar + PADK;
    float4*   sgt   = (float4*)(ssc + PADK);            // [N_GT]
    unsigned* sup   = (unsigned*)(sgt + N_GT);          // [64]
    __shared__ int sNum;

    const int lane = tid & 31;
    const int wid  = tid >> 5;
    const int cslot = blockIdx.x;
    const int Kv = g_Kv[cslot];
    const int W = (Kv + 31) >> 5;

    // reset handshake flag for the next replay (K1 of next launch is
    // stream-ordered after this kernel completes)
    if (tid == 64) g_rank_done[cslot] = 0;

    // zero this class's det slice (2500 float4)
    {
        float4* oz = (float4*)(out + (size_t)cslot * N_ROI * 5);
        for (int i = tid; i < 2500; i += 512) oz[i] = make_float4(0.f, 0.f, 0.f, 0.f);
    }
    for (int a = 0; a < 6; a++) {
        const float4* s4 = (const float4*)&g_soa[a][cslot][0];
        float4* d4 = (float4*)(sx1 + (size_t)a * PADK);
        for (int i = tid; i < PADK / 4; i += 512) d4[i] = s4[i];
    }
    {   // mask copy (uint4 bulk, parallel)
        const uint4* s4 = (const uint4*)&g_mk[cslot][0][0];
        uint4* d4 = (uint4*)smask;
        const int n4 = (Kv * WMASK + 3) >> 2;
        for (int i = tid; i < n4; i += 512) d4[i] = s4[i];
    }
    if (tid < N_GT * 4)
        ((float*)sgt)[tid] = gt_boxes[(tid >> 2) * 5 + (tid & 3)];
    if (tid >= 128 && tid < 192) sup[tid - 128] = 0u;
    if (tid == 0) {
        int nb = num_boxes[0];
        sNum = nb < 0 ? 0 : (nb > N_GT ? N_GT : nb);
    }
    __syncthreads();

    if (Kv > 0) {
        // ---- greedy resolve (warp 0), verified ----
        if (wid == 0) {
            unsigned s_lo = 0u, s_hi = 0u;   // lane owns words lane, lane+32
            const int lastj = (Kv - 1) >> 5;
            const unsigned tailm = (Kv & 31) ? (~0u << (Kv & 31)) : 0u;
            for (int j = 0; j <= lastj; j++) {
                const unsigned* base = smask + (j << 5) * WMASK;
                unsigned d[32];
                #pragma unroll
                for (int b = 0; b < 32; b++) d[b] = base[b * WMASK + j];

                unsigned wj = (j < 32) ? __shfl_sync(0xffffffffu, s_lo, j)
                                       : __shfl_sync(0xffffffffu, s_hi, j - 32);
                if (j == lastj) wj |= tailm;

                unsigned keep = 0u;
                #pragma unroll
                for (int b = 0; b < 32; b++) {
                    if (!(wj & (1u << b))) {
                        keep |= (1u << b);
                        wj |= d[b];
                    }
                }

                if (lane >= j && lane < W) {
                    #pragma unroll
                    for (int b = 0; b < 32; b++) {
                        unsigned m = (unsigned)((int)(keep << (31 - b)) >> 31);
                        s_lo |= base[b * WMASK + lane] & m;
                    }
                }
                if (W > 32) {
                    int l2 = lane + 32;
                    if (l2 >= j && l2 < W) {
                        #pragma unroll
                        for (int b = 0; b < 32; b++) {
                            unsigned m = (unsigned)((int)(keep << (31 - b)) >> 31);
                            s_hi |= base[b * WMASK + l2] & m;
                        }
                    }
                }
                if (j < 32) { if (lane == j) s_lo = wj; }
                else        { if (lane == j - 32) s_hi = wj; }
            }
            sup[lane] = s_lo;
            sup[32 + lane] = s_hi;
        }
        __syncthreads();

        // ---- GT dedup + output (IEEE div kept, matches reference) ----
        float* outc = out + (size_t)cslot * N_ROI * 5;
        const int numgt = sNum;
        for (int i = tid; i < Kv; i += 512) {
            if (!((sup[i >> 5] >> (i & 31)) & 1u)) {
                float bx1 = sx1[i], by1 = sy1[i], bx2 = sx2[i], by2 = sy2[i];
                float ba = sar[i];
                bool hit = false;
                for (int g = 0; g < numgt; g++) {
                    float4 c = sgt[g];
                    float areaB = (c.z - c.x) * (c.w - c.y);
                    float lx = fmaxf(bx1, c.x), ly = fmaxf(by1, c.y);
                    float rx = fminf(bx2, c.z), ry = fminf(by2, c.w);
                    float ww = fmaxf(rx - lx, 0.0f), hh = fmaxf(ry - ly, 0.0f);
                    float inter = ww * hh;
                    float iou = inter / (ba + areaB - inter + 1e-6f);
                    hit = hit || (iou > 0.3f);
                }
                if (!hit) {
                    outc[(size_t)i * 5 + 0] = bx1;
                    outc[(size_t)i * 5 + 1] = by1;
                    outc[(size_t)i * 5 + 2] = bx2;
                    outc[(size_t)i * 5 + 3] = by2;
                    outc[(size_t)i * 5 + 4] = ssc[i];
                }
            }
        }
    }
}

extern "C" void kernel_launch(void* const* d_in, const int* in_sizes, int n_in,
                              void* d_out, int out_size) {
    const float* rois      = (const float*)d_in[0];
    const float* cls_prob  = (const float*)d_in[1];
    const float* bbox_pred = (const float*)d_in[2];
    const float* im_info   = (const float*)d_in[3];
    const float* gt_boxes  = (const float*)d_in[4];
    const int*   num_boxes = (const int*)d_in[5];
    const float* feat      = (const float*)d_in[6];
    const float* feat_org  = (const float*)d_in[7];
    const float* feat_res  = (const float*)d_in[8];
    float* out = (float*)d_out;

    const int smem_res = (int)(PADK * WMASK * sizeof(unsigned)   // 165888
                             + 6 * PADK * sizeof(float)          //  27648
                             + N_GT * sizeof(float4)             //    320
                             + 64 * sizeof(unsigned));           //    256
    static int configured = 0;
    if (!configured) {
        cudaFuncSetAttribute(resolve_out,
                             cudaFuncAttributeMaxDynamicSharedMemorySize,
                             smem_res);
        configured = 1;
    }

    k1_fused<<<459, 512>>>(feat, feat_org, feat_res,
                           cls_prob, rois, bbox_pred, im_info);
    resolve_out<<<21, 512, smem_res>>>(gt_boxes, num_boxes, out);
}